// round 9
// baseline (speedup 1.0000x reference)
#include <cuda_runtime.h>
#include <cuda_fp16.h>
#include <cstdint>
#include <math.h>

#define NB 32
#define NT 2000
#define ED 1024
#define AD 512
#define CCH 32
#define KHALF 50
#define KW 101
#define OD 1024
#define MROWS (NB*NT)     /* 64000 */
#define KEXT (ED + CCH)   /* 1056 */

// ---------------- device scratch (zero-initialized device globals) ----------
__device__ __align__(128) __half g_Ah[(size_t)MROWS * KEXT];  // enc || conv, fp16
__device__ __align__(128) __half g_Bth[AD * KEXT];            // [n][k] fp16
__device__ float g_bias[NB * AD];
__device__ float g_e4[4 * MROWS];                             // per-Nblock partial e
__device__ float g_attn[MROWS];
__device__ float g_ctx[NB * ED];

// ---------------- helpers ----------------
__device__ __forceinline__ void cp16(uint32_t dst, const void* src) {
    asm volatile("cp.async.cg.shared.global [%0], [%1], 16;" :: "r"(dst), "l"(src) : "memory");
}
__device__ __forceinline__ uint32_t smem_u32(const void* p) {
    uint32_t a;
    asm("{ .reg .u64 t; cvta.to.shared.u64 t, %1; cvt.u32.u64 %0, t; }" : "=r"(a) : "l"(p));
    return a;
}
__device__ __forceinline__ uint32_t h2u(__half2 h) {
    return *reinterpret_cast<uint32_t*>(&h);
}
__device__ __forceinline__ float fast_tanh(float x) {
    float y; asm("tanh.approx.f32 %0, %1;" : "=f"(y) : "f"(x)); return y;
}
__device__ __forceinline__ void ldmx4(uint32_t& r0, uint32_t& r1, uint32_t& r2, uint32_t& r3,
                                      uint32_t addr) {
    asm volatile("ldmatrix.sync.aligned.m8n8.x4.shared.b16 {%0,%1,%2,%3}, [%4];"
                 : "=r"(r0), "=r"(r1), "=r"(r2), "=r"(r3) : "r"(addr));
}
__device__ __forceinline__ void mma_f16(float& d0, float& d1, float& d2, float& d3,
                                        uint32_t a0, uint32_t a1, uint32_t a2, uint32_t a3,
                                        uint32_t b0, uint32_t b1) {
    asm volatile(
        "mma.sync.aligned.m16n8k16.row.col.f32.f16.f16.f32 "
        "{%0,%1,%2,%3},{%4,%5,%6,%7},{%8,%9},{%0,%1,%2,%3};"
        : "+f"(d0), "+f"(d1), "+f"(d2), "+f"(d3)
        : "r"(a0), "r"(a1), "r"(a2), "r"(a3), "r"(b0), "r"(b1));
}

// ---------------------------------------------------------------------------
// prep_A: blocks 0..1999 convert enc rows to fp16 (cols 0..1023 of g_Ah);
//         blocks 2000..2255 location conv -> fp16 (cols 1024..1055).
// Masked blocks exit early; those g_Ah rows stay zero-initialized.
// ---------------------------------------------------------------------------
__global__ void prep_A(const float* __restrict__ enc,
                       const float* __restrict__ att_prev,
                       const float* __restrict__ conv_w,
                       const int* __restrict__ enc_len) {
    __shared__ float ap[350];
    __shared__ float wk[CCH * KW];
    const int tid = threadIdx.x;
    if (blockIdx.x < 2000) {
        const int r0 = blockIdx.x * 32;
        const int b0 = r0 / NT, b1 = (r0 + 31) / NT;
        if (b0 == b1 && (r0 - b0 * NT) >= enc_len[b0]) return;
        #pragma unroll 4
        for (int q = 0; q < 32; q++) {
            int u = q * 256 + tid;           // 0..8191 float4 units
            int row = u >> 8, c4 = u & 255;
            float4 v = *reinterpret_cast<const float4*>(enc + (size_t)(r0 + row) * ED + c4 * 4);
            uint2 pk = make_uint2(h2u(__floats2half2_rn(v.x, v.y)),
                                  h2u(__floats2half2_rn(v.z, v.w)));
            *reinterpret_cast<uint2*>(g_Ah + (size_t)(r0 + row) * KEXT + c4 * 4) = pk;
        }
    } else {
        int idx = blockIdx.x - 2000;
        int b = idx >> 3;
        int t0 = (idx & 7) * 250;
        if (t0 >= enc_len[b]) return;
        for (int i = tid; i < 350; i += 256) {
            int gpos = t0 - KHALF + i;
            ap[i] = (gpos >= 0 && gpos < NT) ? att_prev[b * NT + gpos] : 0.f;
        }
        for (int i = tid; i < CCH * KW; i += 256) wk[i] = conv_w[i];
        __syncthreads();
        if (tid < 250) {
            float s[CCH];
            #pragma unroll
            for (int c = 0; c < CCH; c++) s[c] = 0.f;
            for (int k = 0; k < KW; k++) {
                float av = ap[tid + k];
                #pragma unroll
                for (int c = 0; c < CCH; c++) s[c] = fmaf(av, wk[c * KW + k], s[c]);
            }
            uint32_t u32[16];
            #pragma unroll
            for (int k = 0; k < 16; k++) u32[k] = h2u(__floats2half2_rn(s[2*k], s[2*k+1]));
            uint4* dst = reinterpret_cast<uint4*>(g_Ah + (size_t)(b * NT + t0 + tid) * KEXT + ED);
            dst[0] = make_uint4(u32[0], u32[1], u32[2], u32[3]);
            dst[1] = make_uint4(u32[4], u32[5], u32[6], u32[7]);
            dst[2] = make_uint4(u32[8], u32[9], u32[10], u32[11]);
            dst[3] = make_uint4(u32[12], u32[13], u32[14], u32[15]);
        }
    }
}

// ---------------------------------------------------------------------------
// B' = [W_enc ; W_att] transposed K-major -> fp16 g_Bth[n][k]
// ---------------------------------------------------------------------------
__global__ void btrans_kernel(const float* __restrict__ W_enc,
                              const float* __restrict__ W_att) {
    __shared__ float sm[32][33];
    int tx = threadIdx.x, ty = threadIdx.y;
    int k = blockIdx.x * 32 + ty;
    int n = blockIdx.y * 32 + tx;
    sm[ty][tx] = (k < ED) ? W_enc[k * AD + n] : W_att[(k - ED) * AD + n];
    __syncthreads();
    g_Bth[(blockIdx.y * 32 + ty) * KEXT + blockIdx.x * 32 + tx] = __float2half_rn(sm[tx][ty]);
}

// ---------------------------------------------------------------------------
// bias[b,a] = dec_h[b]@W_dec + b_dec + b_enc + b_att   (grid 32 x 2)
// ---------------------------------------------------------------------------
__global__ void bias_kernel(const float* __restrict__ dec_h,
                            const float* __restrict__ W_dec,
                            const float* __restrict__ b_dec,
                            const float* __restrict__ b_enc,
                            const float* __restrict__ b_att) {
    __shared__ float ds[ED];
    int b = blockIdx.x;
    int a = blockIdx.y * 256 + threadIdx.x;
    for (int d = threadIdx.x; d < ED; d += 256) ds[d] = dec_h[b*ED + d];
    __syncthreads();
    float acc = b_dec[a] + b_enc[a] + b_att[a];
    #pragma unroll 16
    for (int d = 0; d < ED; d++) acc = fmaf(ds[d], __ldg(&W_dec[d*AD + a]), acc);
    g_bias[b*AD + a] = acc;
}

// ---------------------------------------------------------------------------
// Main GEMM (mma.sync fp16 m16n8k16 + ldmatrix), masked-CTA early exit.
// ---------------------------------------------------------------------------
#define PITCH 80
#define STAGE 20480            /* A 10240 + B 10240 */
#define DYN_SMEM (3*STAGE)

__global__ __launch_bounds__(256, 2)
void gemm_e_mma(const float* __restrict__ gv, const int* __restrict__ enc_len) {
    extern __shared__ char dyn[];
    __shared__ float gS[128];
    __shared__ float biasS[2][128];
    __shared__ float e_buf[4][128];

    const int tid = threadIdx.x, lane = tid & 31, wid = tid >> 5;
    const int wm = wid >> 2, wn = wid & 3;
    const int g = lane >> 2, c4 = lane & 3;
    const int n0 = blockIdx.x * 128;
    const int m0 = blockIdx.y * 128;
    const int bA = m0 / NT, bB = (m0 + 127) / NT;
    if (bA == bB && (m0 - bA * NT) >= __ldg(&enc_len[bA])) return;

    const uint32_t sbase = smem_u32(dyn);

    if (tid < 128) {
        gS[tid] = gv[n0 + tid];
        biasS[0][tid] = g_bias[bA*AD + n0 + tid];
    } else {
        biasS[1][tid-128] = g_bias[bB*AD + n0 + tid - 128];
    }

    const uint32_t aOff = (uint32_t)((wm*64 + (lane & 15)) * PITCH + ((lane >> 4) & 1) * 16);
    const uint32_t bOff = 10240u +
        (uint32_t)((wn*32 + (lane & 7) + ((lane >> 4) & 1) * 8) * PITCH + ((lane >> 3) & 1) * 16);
    uint32_t aAddr[3], bAddr[3];
    #pragma unroll
    for (int s = 0; s < 3; s++) {
        aAddr[s] = sbase + s*STAGE + aOff;
        bAddr[s] = sbase + s*STAGE + bOff;
    }

    float d[4][4][4];
    #pragma unroll
    for (int i = 0; i < 4; i++)
        #pragma unroll
        for (int jx = 0; jx < 4; jx++)
            #pragma unroll
            for (int qx = 0; qx < 4; qx++) d[i][jx][qx] = 0.f;

    auto issue_tile = [&](int i, int s) {
        uint32_t stA = sbase + s * STAGE;
        uint32_t stB = stA + 10240;
        #pragma unroll
        for (int q = 0; q < 2; q++) {
            int u = q * 256 + tid;           // 0..511
            int row = u >> 2, c16 = u & 3;
            cp16(stA + row * PITCH + c16 * 16,
                 g_Ah + (size_t)(m0 + row) * KEXT + i * 32 + c16 * 8);
            cp16(stB + row * PITCH + c16 * 16,
                 g_Bth + (size_t)(n0 + row) * KEXT + i * 32 + c16 * 8);
        }
        asm volatile("cp.async.commit_group;" ::: "memory");
    };

    issue_tile(0, 0);
    issue_tile(1, 1);

    int st = 0;
    for (int i = 0; i < 33; i++) {
        if (i < 32) asm volatile("cp.async.wait_group 1;" ::: "memory");
        else        asm volatile("cp.async.wait_group 0;" ::: "memory");
        __syncthreads();
        if (i + 2 <= 32) {
            int s2 = st + 2; if (s2 >= 3) s2 -= 3;
            issue_tile(i + 2, s2);
        }

        const uint32_t aS = aAddr[st], bS = bAddr[st];
        #pragma unroll
        for (int ks = 0; ks < 2; ks++) {
            uint32_t br[4][2];
            ldmx4(br[0][0], br[0][1], br[1][0], br[1][1], bS + ks*32);
            ldmx4(br[2][0], br[2][1], br[3][0], br[3][1], bS + 16*PITCH + ks*32);
            #pragma unroll
            for (int mf = 0; mf < 4; mf++) {
                uint32_t a0, a1, a2, a3;
                ldmx4(a0, a1, a2, a3, aS + mf*16*PITCH + ks*32);
                #pragma unroll
                for (int nf = 0; nf < 4; nf++)
                    mma_f16(d[mf][nf][0], d[mf][nf][1], d[mf][nf][2], d[mf][nf][3],
                            a0, a1, a2, a3, br[nf][0], br[nf][1]);
            }
        }
        if (++st == 3) st = 0;
    }

    // ---- epilogue: tanh + g-dot, reduce to e-partial ----
    float pr[4][2];
    #pragma unroll
    for (int mf = 0; mf < 4; mf++) { pr[mf][0] = 0.f; pr[mf][1] = 0.f; }

    #pragma unroll
    for (int mf = 0; mf < 4; mf++) {
        int r_lo = wm * 64 + mf * 16 + g;
        int bi_lo = ((m0 + r_lo) / NT == bA) ? 0 : 1;
        int bi_hi = ((m0 + r_lo + 8) / NT == bA) ? 0 : 1;
        #pragma unroll
        for (int nf = 0; nf < 4; nf++) {
            #pragma unroll
            for (int jx = 0; jx < 4; jx++) {
                int colL = wn * 32 + nf * 8 + 2 * c4 + (jx & 1);
                int bi = (jx >= 2) ? bi_hi : bi_lo;
                float v = d[mf][nf][jx] + biasS[bi][colL];
                pr[mf][jx >= 2] = fmaf(fast_tanh(v), gS[colL], pr[mf][jx >= 2]);
            }
        }
    }
    #pragma unroll
    for (int mf = 0; mf < 4; mf++) {
        #pragma unroll
        for (int h = 0; h < 2; h++) {
            pr[mf][h] += __shfl_xor_sync(0xffffffffu, pr[mf][h], 1);
            pr[mf][h] += __shfl_xor_sync(0xffffffffu, pr[mf][h], 2);
        }
    }
    if (c4 == 0) {
        #pragma unroll
        for (int mf = 0; mf < 4; mf++) {
            e_buf[wn][wm * 64 + mf * 16 + g]     = pr[mf][0];
            e_buf[wn][wm * 64 + mf * 16 + g + 8] = pr[mf][1];
        }
    }
    __syncthreads();
    if (tid < 128)
        g_e4[blockIdx.x * MROWS + m0 + tid] =
            (e_buf[0][tid] + e_buf[1][tid]) + (e_buf[2][tid] + e_buf[3][tid]);
}

// ---------------------------------------------------------------------------
// Masked softmax (SCALING=2); also zeroes g_ctx[b].
// ---------------------------------------------------------------------------
__global__ void softmax_kernel(const int* __restrict__ enc_len,
                               float* __restrict__ attn_dst, int write_dst) {
    __shared__ float red[256];
    __shared__ float eS[NT];
    int b = blockIdx.x;
    int len = enc_len[b];

    for (int d = threadIdx.x; d < ED; d += 256) g_ctx[b*ED + d] = 0.f;
    for (int t = threadIdx.x; t < NT; t += 256) {
        int r = b * NT + t;
        eS[t] = (g_e4[r] + g_e4[MROWS + r]) + (g_e4[2*MROWS + r] + g_e4[3*MROWS + r]);
    }
    __syncthreads();

    float m = -1e30f;
    for (int t = threadIdx.x; t < NT; t += 256)
        if (t < len) m = fmaxf(m, 2.f * eS[t]);
    red[threadIdx.x] = m; __syncthreads();
    for (int s = 128; s > 0; s >>= 1) {
        if (threadIdx.x < s) red[threadIdx.x] = fmaxf(red[threadIdx.x], red[threadIdx.x+s]);
        __syncthreads();
    }
    m = red[0]; __syncthreads();

    float sum = 0.f;
    for (int t = threadIdx.x; t < NT; t += 256)
        if (t < len) sum += expf(2.f * eS[t] - m);
    red[threadIdx.x] = sum; __syncthreads();
    for (int s = 128; s > 0; s >>= 1) {
        if (threadIdx.x < s) red[threadIdx.x] += red[threadIdx.x+s];
        __syncthreads();
    }
    float inv = 1.f / red[0];

    for (int t = threadIdx.x; t < NT; t += 256) {
        float v = (t < len) ? expf(2.f * eS[t] - m) * inv : 0.f;
        g_attn[b*NT + t] = v;
        if (write_dst) attn_dst[b*NT + t] = v;
    }
}

// ---------------------------------------------------------------------------
// ctx[b,d] = sum_t attn[b,t] * enc_fp16[b,t,d].  grid (32, 25); 80 rows/block;
// 8 rows per loop iteration (MLP 8). [measured 24 us in R8]
// ---------------------------------------------------------------------------
__global__ void ctx_kernel(const int* __restrict__ enc_len) {
    int b = blockIdx.x;
    int t0 = blockIdx.y * 80;
    if (t0 >= enc_len[b]) return;
    int d0 = threadIdx.x * 4;
    float a0 = 0.f, a1 = 0.f, a2 = 0.f, a3 = 0.f;
    const __half* base = g_Ah + (size_t)b * NT * KEXT + d0;
    const float* ab = g_attn + b * NT;

    #pragma unroll 1
    for (int i = 0; i < 10; i++) {
        int t = t0 + i * 8;
        float4 wA = *reinterpret_cast<const float4*>(ab + t);
        float4 wB = *reinterpret_cast<const float4*>(ab + t + 4);
        uint2 v[8];
        #pragma unroll
        for (int r = 0; r < 8; r++)
            v[r] = *reinterpret_cast<const uint2*>(base + (size_t)(t + r) * KEXT);
        const float w[8] = {wA.x, wA.y, wA.z, wA.w, wB.x, wB.y, wB.z, wB.w};
        #pragma unroll
        for (int r = 0; r < 8; r++) {
            float2 p = __half22float2(*reinterpret_cast<__half2*>(&v[r].x));
            float2 q = __half22float2(*reinterpret_cast<__half2*>(&v[r].y));
            a0 = fmaf(w[r], p.x, a0); a1 = fmaf(w[r], p.y, a1);
            a2 = fmaf(w[r], q.x, a2); a3 = fmaf(w[r], q.y, a3);
        }
    }
    atomicAdd(&g_ctx[b*ED + d0 + 0], a0);
    atomicAdd(&g_ctx[b*ED + d0 + 1], a1);
    atomicAdd(&g_ctx[b*ED + d0 + 2], a2);
    atomicAdd(&g_ctx[b*ED + d0 + 3], a3);
}

// ---------------------------------------------------------------------------
// c[b,o] = ctx[b]@W_o + b_o   (grid 32 x 4)
// ---------------------------------------------------------------------------
__global__ void out_kernel(const float* __restrict__ W_o,
                           const float* __restrict__ b_o,
                           float* __restrict__ c_dst, int write_dst) {
    __shared__ float cs[ED];
    int b = blockIdx.x;
    int o = blockIdx.y * 256 + threadIdx.x;
    for (int d = threadIdx.x; d < ED; d += 256) cs[d] = g_ctx[b*ED + d];
    __syncthreads();
    if (!write_dst) return;
    float acc = b_o[o];
    #pragma unroll 16
    for (int d = 0; d < ED; d++)
        acc = fmaf(cs[d], __ldg(&W_o[d*OD + o]), acc);
    c_dst[b*OD + o] = acc;
}

// ---------------------------------------------------------------------------
extern "C" void kernel_launch(void* const* d_in, const int* in_sizes, int n_in,
                              void* d_out, int out_size) {
    const float* enc_pad  = (const float*)d_in[0];
    const int*   enc_len  = (const int*)  d_in[1];
    const float* dec_h    = (const float*)d_in[2];
    const float* att_prev = (const float*)d_in[3];
    const float* W_enc    = (const float*)d_in[4];
    const float* b_enc    = (const float*)d_in[5];
    const float* W_dec    = (const float*)d_in[6];
    const float* b_dec    = (const float*)d_in[7];
    const float* W_att    = (const float*)d_in[8];
    const float* b_att    = (const float*)d_in[9];
    const float* conv_w   = (const float*)d_in[10];
    const float* gvec     = (const float*)d_in[11];
    const float* W_o      = (const float*)d_in[12];
    const float* b_o      = (const float*)d_in[13];

    float* out = (float*)d_out;
    float* c_dst    = out;
    float* attn_dst = out;
    int write_c = 0, write_attn = 0;
    if (out_size >= NB*OD + NB*NT) {
        c_dst = out; attn_dst = out + NB*OD;
        write_c = 1; write_attn = 1;
    } else if (out_size == NB*NT) {
        attn_dst = out; write_attn = 1;
    } else {
        c_dst = out; write_c = 1;
    }

    static int smem_set = 0;
    if (!smem_set) {
        cudaFuncSetAttribute(gemm_e_mma, cudaFuncAttributeMaxDynamicSharedMemorySize, DYN_SMEM);
        smem_set = 1;
    }

    prep_A<<<2256, 256>>>(enc_pad, att_prev, conv_w, enc_len);
    btrans_kernel<<<dim3(KEXT/32, AD/32), dim3(32,32)>>>(W_enc, W_att);
    bias_kernel<<<dim3(NB, 2), 256>>>(dec_h, W_dec, b_dec, b_enc, b_att);
    gemm_e_mma<<<dim3(4, 500), 256, DYN_SMEM>>>(gvec, enc_len);
    softmax_kernel<<<NB, 256>>>(enc_len, attn_dst, write_attn);
    ctx_kernel<<<dim3(NB, 25), 256>>>(enc_len);
    out_kernel<<<dim3(NB, 4), 256>>>(W_o, b_o, c_dst, write_c);
}

// round 10
// speedup vs baseline: 1.6882x; 1.6882x over previous
#include <cuda_runtime.h>
#include <cuda_fp16.h>
#include <cstdint>
#include <math.h>

#define NB 32
#define NT 2000
#define ED 1024
#define AD 512
#define CCH 32
#define KHALF 50
#define KW 101
#define OD 1024
#define MROWS (NB*NT)     /* 64000 */
#define KEXT (ED + CCH)   /* 1056 */

// ---------------- device scratch (zero-initialized device globals) ----------
__device__ __align__(128) __half g_Ah[(size_t)MROWS * KEXT];  // enc || conv, fp16
__device__ __align__(128) __half g_Bth[AD * KEXT];            // [n][k] fp16
__device__ float g_bias[NB * AD];
__device__ float g_e4[4 * MROWS];                             // per-Nblock partial e
__device__ float g_attn[MROWS];
__device__ float g_ctx[NB * ED];

// ---------------- helpers ----------------
__device__ __forceinline__ void cp16(uint32_t dst, const void* src) {
    asm volatile("cp.async.cg.shared.global [%0], [%1], 16;" :: "r"(dst), "l"(src) : "memory");
}
__device__ __forceinline__ uint32_t smem_u32(const void* p) {
    uint32_t a;
    asm("{ .reg .u64 t; cvta.to.shared.u64 t, %1; cvt.u32.u64 %0, t; }" : "=r"(a) : "l"(p));
    return a;
}
__device__ __forceinline__ uint32_t h2u(__half2 h) {
    return *reinterpret_cast<uint32_t*>(&h);
}
__device__ __forceinline__ float fast_tanh(float x) {
    float y; asm("tanh.approx.f32 %0, %1;" : "=f"(y) : "f"(x)); return y;
}
__device__ __forceinline__ void ldmx4(uint32_t& r0, uint32_t& r1, uint32_t& r2, uint32_t& r3,
                                      uint32_t addr) {
    asm volatile("ldmatrix.sync.aligned.m8n8.x4.shared.b16 {%0,%1,%2,%3}, [%4];"
                 : "=r"(r0), "=r"(r1), "=r"(r2), "=r"(r3) : "r"(addr));
}
__device__ __forceinline__ void mma_f16(float& d0, float& d1, float& d2, float& d3,
                                        uint32_t a0, uint32_t a1, uint32_t a2, uint32_t a3,
                                        uint32_t b0, uint32_t b1) {
    asm volatile(
        "mma.sync.aligned.m16n8k16.row.col.f32.f16.f16.f32 "
        "{%0,%1,%2,%3},{%4,%5,%6,%7},{%8,%9},{%0,%1,%2,%3};"
        : "+f"(d0), "+f"(d1), "+f"(d2), "+f"(d3)
        : "r"(a0), "r"(a1), "r"(a2), "r"(a3), "r"(b0), "r"(b1));
}

// ---------------------------------------------------------------------------
// prep_A: blocks 0..1999 convert enc rows to fp16 (cols 0..1023 of g_Ah);
//         blocks 2000..2255 location conv -> fp16 (cols 1024..1055).
// Masked blocks exit early; those g_Ah rows stay zero-initialized.
// ---------------------------------------------------------------------------
__global__ void prep_A(const float* __restrict__ enc,
                       const float* __restrict__ att_prev,
                       const float* __restrict__ conv_w,
                       const int* __restrict__ enc_len) {
    __shared__ float ap[350];
    __shared__ float wk[CCH * KW];
    const int tid = threadIdx.x;
    if (blockIdx.x < 2000) {
        const int r0 = blockIdx.x * 32;
        const int b0 = r0 / NT, b1 = (r0 + 31) / NT;
        if (b0 == b1 && (r0 - b0 * NT) >= enc_len[b0]) return;
        #pragma unroll 4
        for (int q = 0; q < 32; q++) {
            int u = q * 256 + tid;           // 0..8191 float4 units
            int row = u >> 8, c4 = u & 255;
            float4 v = *reinterpret_cast<const float4*>(enc + (size_t)(r0 + row) * ED + c4 * 4);
            uint2 pk = make_uint2(h2u(__floats2half2_rn(v.x, v.y)),
                                  h2u(__floats2half2_rn(v.z, v.w)));
            *reinterpret_cast<uint2*>(g_Ah + (size_t)(r0 + row) * KEXT + c4 * 4) = pk;
        }
    } else {
        int idx = blockIdx.x - 2000;
        int b = idx >> 3;
        int t0 = (idx & 7) * 250;
        if (t0 >= enc_len[b]) return;
        for (int i = tid; i < 350; i += 256) {
            int gpos = t0 - KHALF + i;
            ap[i] = (gpos >= 0 && gpos < NT) ? att_prev[b * NT + gpos] : 0.f;
        }
        for (int i = tid; i < CCH * KW; i += 256) wk[i] = conv_w[i];
        __syncthreads();
        if (tid < 250) {
            float s[CCH];
            #pragma unroll
            for (int c = 0; c < CCH; c++) s[c] = 0.f;
            for (int k = 0; k < KW; k++) {
                float av = ap[tid + k];
                #pragma unroll
                for (int c = 0; c < CCH; c++) s[c] = fmaf(av, wk[c * KW + k], s[c]);
            }
            uint32_t u32[16];
            #pragma unroll
            for (int k = 0; k < 16; k++) u32[k] = h2u(__floats2half2_rn(s[2*k], s[2*k+1]));
            uint4* dst = reinterpret_cast<uint4*>(g_Ah + (size_t)(b * NT + t0 + tid) * KEXT + ED);
            dst[0] = make_uint4(u32[0], u32[1], u32[2], u32[3]);
            dst[1] = make_uint4(u32[4], u32[5], u32[6], u32[7]);
            dst[2] = make_uint4(u32[8], u32[9], u32[10], u32[11]);
            dst[3] = make_uint4(u32[12], u32[13], u32[14], u32[15]);
        }
    }
}

// ---------------------------------------------------------------------------
// B' = [W_enc ; W_att] transposed K-major -> fp16 g_Bth[n][k]
// ---------------------------------------------------------------------------
__global__ void btrans_kernel(const float* __restrict__ W_enc,
                              const float* __restrict__ W_att) {
    __shared__ float sm[32][33];
    int tx = threadIdx.x, ty = threadIdx.y;
    int k = blockIdx.x * 32 + ty;
    int n = blockIdx.y * 32 + tx;
    sm[ty][tx] = (k < ED) ? W_enc[k * AD + n] : W_att[(k - ED) * AD + n];
    __syncthreads();
    g_Bth[(blockIdx.y * 32 + ty) * KEXT + blockIdx.x * 32 + tx] = __float2half_rn(sm[tx][ty]);
}

// ---------------------------------------------------------------------------
// bias[b,a] = dec_h[b]@W_dec + b_dec + b_enc + b_att   (grid 32 x 2)
// ---------------------------------------------------------------------------
__global__ void bias_kernel(const float* __restrict__ dec_h,
                            const float* __restrict__ W_dec,
                            const float* __restrict__ b_dec,
                            const float* __restrict__ b_enc,
                            const float* __restrict__ b_att) {
    __shared__ float ds[ED];
    int b = blockIdx.x;
    int a = blockIdx.y * 256 + threadIdx.x;
    for (int d = threadIdx.x; d < ED; d += 256) ds[d] = dec_h[b*ED + d];
    __syncthreads();
    float acc = b_dec[a] + b_enc[a] + b_att[a];
    #pragma unroll 8
    for (int d = 0; d < ED; d++) acc = fmaf(ds[d], W_dec[d*AD + a], acc);
    g_bias[b*AD + a] = acc;
}

// ---------------------------------------------------------------------------
// Main GEMM (mma.sync fp16 m16n8k16 + ldmatrix), masked-CTA early exit.
// ---------------------------------------------------------------------------
#define PITCH 80
#define STAGE 20480            /* A 10240 + B 10240 */
#define DYN_SMEM (3*STAGE)

__global__ __launch_bounds__(256, 2)
void gemm_e_mma(const float* __restrict__ gv, const int* __restrict__ enc_len) {
    extern __shared__ char dyn[];
    __shared__ float gS[128];
    __shared__ float biasS[2][128];
    __shared__ float e_buf[4][128];

    const int tid = threadIdx.x, lane = tid & 31, wid = tid >> 5;
    const int wm = wid >> 2, wn = wid & 3;
    const int g = lane >> 2, c4 = lane & 3;
    const int n0 = blockIdx.x * 128;
    const int m0 = blockIdx.y * 128;
    const int bA = m0 / NT, bB = (m0 + 127) / NT;
    if (bA == bB && (m0 - bA * NT) >= __ldg(&enc_len[bA])) return;

    const uint32_t sbase = smem_u32(dyn);

    if (tid < 128) {
        gS[tid] = gv[n0 + tid];
        biasS[0][tid] = g_bias[bA*AD + n0 + tid];
    } else {
        biasS[1][tid-128] = g_bias[bB*AD + n0 + tid - 128];
    }

    const uint32_t aOff = (uint32_t)((wm*64 + (lane & 15)) * PITCH + ((lane >> 4) & 1) * 16);
    const uint32_t bOff = 10240u +
        (uint32_t)((wn*32 + (lane & 7) + ((lane >> 4) & 1) * 8) * PITCH + ((lane >> 3) & 1) * 16);
    uint32_t aAddr[3], bAddr[3];
    #pragma unroll
    for (int s = 0; s < 3; s++) {
        aAddr[s] = sbase + s*STAGE + aOff;
        bAddr[s] = sbase + s*STAGE + bOff;
    }

    float d[4][4][4];
    #pragma unroll
    for (int i = 0; i < 4; i++)
        #pragma unroll
        for (int jx = 0; jx < 4; jx++)
            #pragma unroll
            for (int qx = 0; qx < 4; qx++) d[i][jx][qx] = 0.f;

    auto issue_tile = [&](int i, int s) {
        uint32_t stA = sbase + s * STAGE;
        uint32_t stB = stA + 10240;
        #pragma unroll
        for (int q = 0; q < 2; q++) {
            int u = q * 256 + tid;           // 0..511
            int row = u >> 2, c16 = u & 3;
            cp16(stA + row * PITCH + c16 * 16,
                 g_Ah + (size_t)(m0 + row) * KEXT + i * 32 + c16 * 8);
            cp16(stB + row * PITCH + c16 * 16,
                 g_Bth + (size_t)(n0 + row) * KEXT + i * 32 + c16 * 8);
        }
        asm volatile("cp.async.commit_group;" ::: "memory");
    };

    issue_tile(0, 0);
    issue_tile(1, 1);

    int st = 0;
    for (int i = 0; i < 33; i++) {
        if (i < 32) asm volatile("cp.async.wait_group 1;" ::: "memory");
        else        asm volatile("cp.async.wait_group 0;" ::: "memory");
        __syncthreads();
        if (i + 2 <= 32) {
            int s2 = st + 2; if (s2 >= 3) s2 -= 3;
            issue_tile(i + 2, s2);
        }

        const uint32_t aS = aAddr[st], bS = bAddr[st];
        #pragma unroll
        for (int ks = 0; ks < 2; ks++) {
            uint32_t br[4][2];
            ldmx4(br[0][0], br[0][1], br[1][0], br[1][1], bS + ks*32);
            ldmx4(br[2][0], br[2][1], br[3][0], br[3][1], bS + 16*PITCH + ks*32);
            #pragma unroll
            for (int mf = 0; mf < 4; mf++) {
                uint32_t a0, a1, a2, a3;
                ldmx4(a0, a1, a2, a3, aS + mf*16*PITCH + ks*32);
                #pragma unroll
                for (int nf = 0; nf < 4; nf++)
                    mma_f16(d[mf][nf][0], d[mf][nf][1], d[mf][nf][2], d[mf][nf][3],
                            a0, a1, a2, a3, br[nf][0], br[nf][1]);
            }
        }
        if (++st == 3) st = 0;
    }

    // ---- epilogue: tanh + g-dot, reduce to e-partial ----
    float pr[4][2];
    #pragma unroll
    for (int mf = 0; mf < 4; mf++) { pr[mf][0] = 0.f; pr[mf][1] = 0.f; }

    #pragma unroll
    for (int mf = 0; mf < 4; mf++) {
        int r_lo = wm * 64 + mf * 16 + g;
        int bi_lo = ((m0 + r_lo) / NT == bA) ? 0 : 1;
        int bi_hi = ((m0 + r_lo + 8) / NT == bA) ? 0 : 1;
        #pragma unroll
        for (int nf = 0; nf < 4; nf++) {
            #pragma unroll
            for (int jx = 0; jx < 4; jx++) {
                int colL = wn * 32 + nf * 8 + 2 * c4 + (jx & 1);
                int bi = (jx >= 2) ? bi_hi : bi_lo;
                float v = d[mf][nf][jx] + biasS[bi][colL];
                pr[mf][jx >= 2] = fmaf(fast_tanh(v), gS[colL], pr[mf][jx >= 2]);
            }
        }
    }
    #pragma unroll
    for (int mf = 0; mf < 4; mf++) {
        #pragma unroll
        for (int h = 0; h < 2; h++) {
            pr[mf][h] += __shfl_xor_sync(0xffffffffu, pr[mf][h], 1);
            pr[mf][h] += __shfl_xor_sync(0xffffffffu, pr[mf][h], 2);
        }
    }
    if (c4 == 0) {
        #pragma unroll
        for (int mf = 0; mf < 4; mf++) {
            e_buf[wn][wm * 64 + mf * 16 + g]     = pr[mf][0];
            e_buf[wn][wm * 64 + mf * 16 + g + 8] = pr[mf][1];
        }
    }
    __syncthreads();
    if (tid < 128)
        g_e4[blockIdx.x * MROWS + m0 + tid] =
            (e_buf[0][tid] + e_buf[1][tid]) + (e_buf[2][tid] + e_buf[3][tid]);
}

// ---------------------------------------------------------------------------
// Masked softmax (SCALING=2); also zeroes g_ctx[b].
// ---------------------------------------------------------------------------
__global__ void softmax_kernel(const int* __restrict__ enc_len,
                               float* __restrict__ attn_dst, int write_dst) {
    __shared__ float red[256];
    __shared__ float eS[NT];
    int b = blockIdx.x;
    int len = enc_len[b];

    for (int d = threadIdx.x; d < ED; d += 256) g_ctx[b*ED + d] = 0.f;
    for (int t = threadIdx.x; t < NT; t += 256) {
        int r = b * NT + t;
        eS[t] = (g_e4[r] + g_e4[MROWS + r]) + (g_e4[2*MROWS + r] + g_e4[3*MROWS + r]);
    }
    __syncthreads();

    float m = -1e30f;
    for (int t = threadIdx.x; t < NT; t += 256)
        if (t < len) m = fmaxf(m, 2.f * eS[t]);
    red[threadIdx.x] = m; __syncthreads();
    for (int s = 128; s > 0; s >>= 1) {
        if (threadIdx.x < s) red[threadIdx.x] = fmaxf(red[threadIdx.x], red[threadIdx.x+s]);
        __syncthreads();
    }
    m = red[0]; __syncthreads();

    float sum = 0.f;
    for (int t = threadIdx.x; t < NT; t += 256)
        if (t < len) sum += expf(2.f * eS[t] - m);
    red[threadIdx.x] = sum; __syncthreads();
    for (int s = 128; s > 0; s >>= 1) {
        if (threadIdx.x < s) red[threadIdx.x] += red[threadIdx.x+s];
        __syncthreads();
    }
    float inv = 1.f / red[0];

    for (int t = threadIdx.x; t < NT; t += 256) {
        float v = (t < len) ? expf(2.f * eS[t] - m) * inv : 0.f;
        g_attn[b*NT + t] = v;
        if (write_dst) attn_dst[b*NT + t] = v;
    }
}

// ---------------------------------------------------------------------------
// ctx[b,d] = sum_t attn[b,t] * enc_fp16[b,t,d].  grid (32, 25); 80 rows/block;
// 8 rows per loop iteration (MLP 8). [measured 24 us, DRAM 58%, in R8]
// ---------------------------------------------------------------------------
__global__ void ctx_kernel(const int* __restrict__ enc_len) {
    int b = blockIdx.x;
    int t0 = blockIdx.y * 80;
    if (t0 >= enc_len[b]) return;
    int d0 = threadIdx.x * 4;
    float a0 = 0.f, a1 = 0.f, a2 = 0.f, a3 = 0.f;
    const __half* base = g_Ah + (size_t)b * NT * KEXT + d0;
    const float* ab = g_attn + b * NT;

    #pragma unroll 1
    for (int i = 0; i < 10; i++) {
        int t = t0 + i * 8;
        float4 wA = *reinterpret_cast<const float4*>(ab + t);
        float4 wB = *reinterpret_cast<const float4*>(ab + t + 4);
        uint2 v[8];
        #pragma unroll
        for (int r = 0; r < 8; r++)
            v[r] = *reinterpret_cast<const uint2*>(base + (size_t)(t + r) * KEXT);
        const float w[8] = {wA.x, wA.y, wA.z, wA.w, wB.x, wB.y, wB.z, wB.w};
        #pragma unroll
        for (int r = 0; r < 8; r++) {
            float2 p = __half22float2(*reinterpret_cast<__half2*>(&v[r].x));
            float2 q = __half22float2(*reinterpret_cast<__half2*>(&v[r].y));
            a0 = fmaf(w[r], p.x, a0); a1 = fmaf(w[r], p.y, a1);
            a2 = fmaf(w[r], q.x, a2); a3 = fmaf(w[r], q.y, a3);
        }
    }
    atomicAdd(&g_ctx[b*ED + d0 + 0], a0);
    atomicAdd(&g_ctx[b*ED + d0 + 1], a1);
    atomicAdd(&g_ctx[b*ED + d0 + 2], a2);
    atomicAdd(&g_ctx[b*ED + d0 + 3], a3);
}

// ---------------------------------------------------------------------------
// c[b,o] = ctx[b]@W_o + b_o   (grid 32 x 4)
// ---------------------------------------------------------------------------
__global__ void out_kernel(const float* __restrict__ W_o,
                           const float* __restrict__ b_o,
                           float* __restrict__ c_dst, int write_dst) {
    __shared__ float cs[ED];
    int b = blockIdx.x;
    int o = blockIdx.y * 256 + threadIdx.x;
    for (int d = threadIdx.x; d < ED; d += 256) cs[d] = g_ctx[b*ED + d];
    __syncthreads();
    if (!write_dst) return;
    float acc = b_o[o];
    #pragma unroll 8
    for (int d = 0; d < ED; d++)
        acc = fmaf(cs[d], W_o[d*OD + o], acc);
    c_dst[b*OD + o] = acc;
}

// ---------------------------------------------------------------------------
extern "C" void kernel_launch(void* const* d_in, const int* in_sizes, int n_in,
                              void* d_out, int out_size) {
    const float* enc_pad  = (const float*)d_in[0];
    const int*   enc_len  = (const int*)  d_in[1];
    const float* dec_h    = (const float*)d_in[2];
    const float* att_prev = (const float*)d_in[3];
    const float* W_enc    = (const float*)d_in[4];
    const float* b_enc    = (const float*)d_in[5];
    const float* W_dec    = (const float*)d_in[6];
    const float* b_dec    = (const float*)d_in[7];
    const float* W_att    = (const float*)d_in[8];
    const float* b_att    = (const float*)d_in[9];
    const float* conv_w   = (const float*)d_in[10];
    const float* gvec     = (const float*)d_in[11];
    const float* W_o      = (const float*)d_in[12];
    const float* b_o      = (const float*)d_in[13];

    float* out = (float*)d_out;
    float* c_dst    = out;
    float* attn_dst = out;
    int write_c = 0, write_attn = 0;
    if (out_size >= NB*OD + NB*NT) {
        c_dst = out; attn_dst = out + NB*OD;
        write_c = 1; write_attn = 1;
    } else if (out_size == NB*NT) {
        attn_dst = out; write_attn = 1;
    } else {
        c_dst = out; write_c = 1;
    }

    static int smem_set = 0;
    if (!smem_set) {
        cudaFuncSetAttribute(gemm_e_mma, cudaFuncAttributeMaxDynamicSharedMemorySize, DYN_SMEM);
        smem_set = 1;
    }

    prep_A<<<2256, 256>>>(enc_pad, att_prev, conv_w, enc_len);
    btrans_kernel<<<dim3(KEXT/32, AD/32), dim3(32,32)>>>(W_enc, W_att);
    bias_kernel<<<dim3(NB, 2), 256>>>(dec_h, W_dec, b_dec, b_enc, b_att);
    gemm_e_mma<<<dim3(4, 500), 256, DYN_SMEM>>>(gvec, enc_len);
    softmax_kernel<<<NB, 256>>>(enc_len, attn_dst, write_attn);
    ctx_kernel<<<dim3(NB, 25), 256>>>(enc_len);
    out_kernel<<<dim3(NB, 4), 256>>>(W_o, b_o, c_dst, write_c);
}

// round 11
// speedup vs baseline: 1.9816x; 1.1738x over previous
#include <cuda_runtime.h>
#include <cuda_fp16.h>
#include <cstdint>
#include <math.h>

#define NB 32
#define NT 2000
#define ED 1024
#define AD 512
#define CCH 32
#define KHALF 50
#define KW 101
#define OD 1024
#define MROWS (NB*NT)     /* 64000 */
#define KEXT (ED + CCH)   /* 1056 */

// ---------------- device scratch (zero-initialized device globals) ----------
__device__ __align__(128) __half g_Ah[(size_t)MROWS * KEXT];  // enc || conv, fp16
__device__ __align__(128) __half g_Bth[AD * KEXT];            // [n][k] fp16
__device__ float g_bias[NB * AD];
__device__ float g_e4[4 * MROWS];                             // per-Nblock partial e
__device__ float g_ctx[NB * ED];

// ---------------- helpers ----------------
__device__ __forceinline__ void cp16(uint32_t dst, const void* src) {
    asm volatile("cp.async.cg.shared.global [%0], [%1], 16;" :: "r"(dst), "l"(src) : "memory");
}
__device__ __forceinline__ uint32_t smem_u32(const void* p) {
    uint32_t a;
    asm("{ .reg .u64 t; cvta.to.shared.u64 t, %1; cvt.u32.u64 %0, t; }" : "=r"(a) : "l"(p));
    return a;
}
__device__ __forceinline__ uint32_t h2u(__half2 h) {
    return *reinterpret_cast<uint32_t*>(&h);
}
__device__ __forceinline__ float fast_tanh(float x) {
    float y; asm("tanh.approx.f32 %0, %1;" : "=f"(y) : "f"(x)); return y;
}
__device__ __forceinline__ void ldmx4(uint32_t& r0, uint32_t& r1, uint32_t& r2, uint32_t& r3,
                                      uint32_t addr) {
    asm volatile("ldmatrix.sync.aligned.m8n8.x4.shared.b16 {%0,%1,%2,%3}, [%4];"
                 : "=r"(r0), "=r"(r1), "=r"(r2), "=r"(r3) : "r"(addr));
}
__device__ __forceinline__ void mma_f16(float& d0, float& d1, float& d2, float& d3,
                                        uint32_t a0, uint32_t a1, uint32_t a2, uint32_t a3,
                                        uint32_t b0, uint32_t b1) {
    asm volatile(
        "mma.sync.aligned.m16n8k16.row.col.f32.f16.f16.f32 "
        "{%0,%1,%2,%3},{%4,%5,%6,%7},{%8,%9},{%0,%1,%2,%3};"
        : "+f"(d0), "+f"(d1), "+f"(d2), "+f"(d3)
        : "r"(a0), "r"(a1), "r"(a2), "r"(a3), "r"(b0), "r"(b1));
}

// ---------------------------------------------------------------------------
// prep_A: blocks 0..1999 convert enc rows to fp16 (cols 0..1023 of g_Ah);
//         blocks 2000..2255 location conv -> fp16 (cols 1024..1055).
// Masked blocks exit early; those g_Ah rows stay zero-initialized.
// ---------------------------------------------------------------------------
__global__ void prep_A(const float* __restrict__ enc,
                       const float* __restrict__ att_prev,
                       const float* __restrict__ conv_w,
                       const int* __restrict__ enc_len) {
    __shared__ float ap[350];
    __shared__ float wk[CCH * KW];
    const int tid = threadIdx.x;
    if (blockIdx.x < 2000) {
        const int r0 = blockIdx.x * 32;
        const int b0 = r0 / NT, b1 = (r0 + 31) / NT;
        if (b0 == b1 && (r0 - b0 * NT) >= enc_len[b0]) return;
        #pragma unroll 4
        for (int q = 0; q < 32; q++) {
            int u = q * 256 + tid;           // 0..8191 float4 units
            int row = u >> 8, c4 = u & 255;
            float4 v = *reinterpret_cast<const float4*>(enc + (size_t)(r0 + row) * ED + c4 * 4);
            uint2 pk = make_uint2(h2u(__floats2half2_rn(v.x, v.y)),
                                  h2u(__floats2half2_rn(v.z, v.w)));
            *reinterpret_cast<uint2*>(g_Ah + (size_t)(r0 + row) * KEXT + c4 * 4) = pk;
        }
    } else {
        int idx = blockIdx.x - 2000;
        int b = idx >> 3;
        int t0 = (idx & 7) * 250;
        if (t0 >= enc_len[b]) return;
        for (int i = tid; i < 350; i += 256) {
            int gpos = t0 - KHALF + i;
            ap[i] = (gpos >= 0 && gpos < NT) ? att_prev[b * NT + gpos] : 0.f;
        }
        for (int i = tid; i < CCH * KW; i += 256) wk[i] = conv_w[i];
        __syncthreads();
        if (tid < 250) {
            float s[CCH];
            #pragma unroll
            for (int c = 0; c < CCH; c++) s[c] = 0.f;
            for (int k = 0; k < KW; k++) {
                float av = ap[tid + k];
                #pragma unroll
                for (int c = 0; c < CCH; c++) s[c] = fmaf(av, wk[c * KW + k], s[c]);
            }
            uint32_t u32[16];
            #pragma unroll
            for (int k = 0; k < 16; k++) u32[k] = h2u(__floats2half2_rn(s[2*k], s[2*k+1]));
            uint4* dst = reinterpret_cast<uint4*>(g_Ah + (size_t)(b * NT + t0 + tid) * KEXT + ED);
            dst[0] = make_uint4(u32[0], u32[1], u32[2], u32[3]);
            dst[1] = make_uint4(u32[4], u32[5], u32[6], u32[7]);
            dst[2] = make_uint4(u32[8], u32[9], u32[10], u32[11]);
            dst[3] = make_uint4(u32[12], u32[13], u32[14], u32[15]);
        }
    }
}

// ---------------------------------------------------------------------------
// B' = [W_enc ; W_att] transposed K-major -> fp16 g_Bth[n][k]
// ---------------------------------------------------------------------------
__global__ void btrans_kernel(const float* __restrict__ W_enc,
                              const float* __restrict__ W_att) {
    __shared__ float sm[32][33];
    int tx = threadIdx.x, ty = threadIdx.y;
    int k = blockIdx.x * 32 + ty;
    int n = blockIdx.y * 32 + tx;
    sm[ty][tx] = (k < ED) ? W_enc[k * AD + n] : W_att[(k - ED) * AD + n];
    __syncthreads();
    g_Bth[(blockIdx.y * 32 + ty) * KEXT + blockIdx.x * 32 + tx] = __float2half_rn(sm[tx][ty]);
}

// ---------------------------------------------------------------------------
// bias: grid (4 bgroup, 8 agroup), block 256 = 64 a-cols x 4 d-slices.
// bias[b,a] = dec_h[b]@W_dec + b_dec + b_enc + b_att for 8 b's per block.
// Also zeroes g_ctx (32 blocks x 1024 floats).
// ---------------------------------------------------------------------------
__global__ void bias_kernel(const float* __restrict__ dec_h,
                            const float* __restrict__ W_dec,
                            const float* __restrict__ b_dec,
                            const float* __restrict__ b_enc,
                            const float* __restrict__ b_att) {
    __shared__ float ds[8][ED];        // 32KB
    __shared__ float red[4][64][8];    // 8KB
    const int tid = threadIdx.x;
    const int bg = blockIdx.x;
    const int al = tid & 63;
    const int a = blockIdx.y * 64 + al;
    const int sl = tid >> 6;

    for (int i = tid; i < 2048; i += 256)
        reinterpret_cast<float4*>(&ds[0][0])[i] =
            reinterpret_cast<const float4*>(dec_h + (size_t)bg * 8 * ED)[i];
    {
        int blk = bg * 8 + blockIdx.y;   // 0..31
        for (int i = tid; i < 1024; i += 256) g_ctx[blk * 1024 + i] = 0.f;
    }
    __syncthreads();

    float acc[8];
    #pragma unroll
    for (int j = 0; j < 8; j++) acc[j] = 0.f;
    #pragma unroll 1
    for (int dd = 0; dd < 256; dd += 8) {
        int d = sl * 256 + dd;
        float w[8];
        #pragma unroll
        for (int u = 0; u < 8; u++) w[u] = W_dec[(d + u) * AD + a];
        #pragma unroll
        for (int j = 0; j < 8; j++)
            #pragma unroll
            for (int u = 0; u < 8; u++)
                acc[j] = fmaf(ds[j][d + u], w[u], acc[j]);
    }
    #pragma unroll
    for (int j = 0; j < 8; j++) red[sl][al][j] = acc[j];
    __syncthreads();
    if (sl == 0) {
        float base = b_dec[a] + b_enc[a] + b_att[a];
        #pragma unroll
        for (int j = 0; j < 8; j++)
            g_bias[(bg * 8 + j) * AD + a] =
                base + (red[0][al][j] + red[1][al][j]) + (red[2][al][j] + red[3][al][j]);
    }
}

// ---------------------------------------------------------------------------
// Main GEMM (mma.sync fp16 m16n8k16 + ldmatrix), masked-CTA early exit.
// ---------------------------------------------------------------------------
#define PITCH 80
#define STAGE 20480            /* A 10240 + B 10240 */
#define DYN_SMEM (3*STAGE)

__global__ __launch_bounds__(256, 2)
void gemm_e_mma(const float* __restrict__ gv, const int* __restrict__ enc_len) {
    extern __shared__ char dyn[];
    __shared__ float gS[128];
    __shared__ float biasS[2][128];
    __shared__ float e_buf[4][128];

    const int tid = threadIdx.x, lane = tid & 31, wid = tid >> 5;
    const int wm = wid >> 2, wn = wid & 3;
    const int g = lane >> 2, c4 = lane & 3;
    const int n0 = blockIdx.x * 128;
    const int m0 = blockIdx.y * 128;
    const int bA = m0 / NT, bB = (m0 + 127) / NT;
    if (bA == bB && (m0 - bA * NT) >= __ldg(&enc_len[bA])) return;

    const uint32_t sbase = smem_u32(dyn);

    if (tid < 128) {
        gS[tid] = gv[n0 + tid];
        biasS[0][tid] = g_bias[bA*AD + n0 + tid];
    } else {
        biasS[1][tid-128] = g_bias[bB*AD + n0 + tid - 128];
    }

    const uint32_t aOff = (uint32_t)((wm*64 + (lane & 15)) * PITCH + ((lane >> 4) & 1) * 16);
    const uint32_t bOff = 10240u +
        (uint32_t)((wn*32 + (lane & 7) + ((lane >> 4) & 1) * 8) * PITCH + ((lane >> 3) & 1) * 16);
    uint32_t aAddr[3], bAddr[3];
    #pragma unroll
    for (int s = 0; s < 3; s++) {
        aAddr[s] = sbase + s*STAGE + aOff;
        bAddr[s] = sbase + s*STAGE + bOff;
    }

    float d[4][4][4];
    #pragma unroll
    for (int i = 0; i < 4; i++)
        #pragma unroll
        for (int jx = 0; jx < 4; jx++)
            #pragma unroll
            for (int qx = 0; qx < 4; qx++) d[i][jx][qx] = 0.f;

    auto issue_tile = [&](int i, int s) {
        uint32_t stA = sbase + s * STAGE;
        uint32_t stB = stA + 10240;
        #pragma unroll
        for (int q = 0; q < 2; q++) {
            int u = q * 256 + tid;           // 0..511
            int row = u >> 2, c16 = u & 3;
            cp16(stA + row * PITCH + c16 * 16,
                 g_Ah + (size_t)(m0 + row) * KEXT + i * 32 + c16 * 8);
            cp16(stB + row * PITCH + c16 * 16,
                 g_Bth + (size_t)(n0 + row) * KEXT + i * 32 + c16 * 8);
        }
        asm volatile("cp.async.commit_group;" ::: "memory");
    };

    issue_tile(0, 0);
    issue_tile(1, 1);

    int st = 0;
    for (int i = 0; i < 33; i++) {
        if (i < 32) asm volatile("cp.async.wait_group 1;" ::: "memory");
        else        asm volatile("cp.async.wait_group 0;" ::: "memory");
        __syncthreads();
        if (i + 2 <= 32) {
            int s2 = st + 2; if (s2 >= 3) s2 -= 3;
            issue_tile(i + 2, s2);
        }

        const uint32_t aS = aAddr[st], bS = bAddr[st];
        #pragma unroll
        for (int ks = 0; ks < 2; ks++) {
            uint32_t br[4][2];
            ldmx4(br[0][0], br[0][1], br[1][0], br[1][1], bS + ks*32);
            ldmx4(br[2][0], br[2][1], br[3][0], br[3][1], bS + 16*PITCH + ks*32);
            #pragma unroll
            for (int mf = 0; mf < 4; mf++) {
                uint32_t a0, a1, a2, a3;
                ldmx4(a0, a1, a2, a3, aS + mf*16*PITCH + ks*32);
                #pragma unroll
                for (int nf = 0; nf < 4; nf++)
                    mma_f16(d[mf][nf][0], d[mf][nf][1], d[mf][nf][2], d[mf][nf][3],
                            a0, a1, a2, a3, br[nf][0], br[nf][1]);
            }
        }
        if (++st == 3) st = 0;
    }

    // ---- epilogue: tanh + g-dot, reduce to e-partial ----
    float pr[4][2];
    #pragma unroll
    for (int mf = 0; mf < 4; mf++) { pr[mf][0] = 0.f; pr[mf][1] = 0.f; }

    #pragma unroll
    for (int mf = 0; mf < 4; mf++) {
        int r_lo = wm * 64 + mf * 16 + g;
        int bi_lo = ((m0 + r_lo) / NT == bA) ? 0 : 1;
        int bi_hi = ((m0 + r_lo + 8) / NT == bA) ? 0 : 1;
        #pragma unroll
        for (int nf = 0; nf < 4; nf++) {
            #pragma unroll
            for (int jx = 0; jx < 4; jx++) {
                int colL = wn * 32 + nf * 8 + 2 * c4 + (jx & 1);
                int bi = (jx >= 2) ? bi_hi : bi_lo;
                float v = d[mf][nf][jx] + biasS[bi][colL];
                pr[mf][jx >= 2] = fmaf(fast_tanh(v), gS[colL], pr[mf][jx >= 2]);
            }
        }
    }
    #pragma unroll
    for (int mf = 0; mf < 4; mf++) {
        #pragma unroll
        for (int h = 0; h < 2; h++) {
            pr[mf][h] += __shfl_xor_sync(0xffffffffu, pr[mf][h], 1);
            pr[mf][h] += __shfl_xor_sync(0xffffffffu, pr[mf][h], 2);
        }
    }
    if (c4 == 0) {
        #pragma unroll
        for (int mf = 0; mf < 4; mf++) {
            e_buf[wn][wm * 64 + mf * 16 + g]     = pr[mf][0];
            e_buf[wn][wm * 64 + mf * 16 + g + 8] = pr[mf][1];
        }
    }
    __syncthreads();
    if (tid < 128)
        g_e4[blockIdx.x * MROWS + m0 + tid] =
            (e_buf[0][tid] + e_buf[1][tid]) + (e_buf[2][tid] + e_buf[3][tid]);
}

// ---------------------------------------------------------------------------
// ctx_fused: per (b, chunk of 80 t): recompute row softmax stats from g_e4
// (identical order per b -> deterministic), emit attn for own chunk, then
// ctx partial accumulation. Replaces separate softmax kernel + g_attn.
// ---------------------------------------------------------------------------
__global__ void ctx_fused(const int* __restrict__ enc_len,
                          float* __restrict__ attn_dst, int write_attn) {
    __shared__ float red[256];
    __shared__ float aw[80];
    const int b = blockIdx.x, chunk = blockIdx.y;
    const int len = enc_len[b];
    const int t0 = chunk * 80;
    const int tid = threadIdx.x;

    if (t0 >= len) {            // fully masked: attn zeros only
        if (write_attn && tid < 80) attn_dst[b*NT + t0 + tid] = 0.f;
        return;
    }
    const float* e0 = g_e4 + b * NT;

    float m = -1e30f;
    for (int t = tid; t < NT; t += 256)
        if (t < len) {
            float e = (e0[t] + e0[MROWS + t]) + (e0[2*MROWS + t] + e0[3*MROWS + t]);
            m = fmaxf(m, 2.f * e);
        }
    red[tid] = m; __syncthreads();
    for (int s = 128; s > 0; s >>= 1) {
        if (tid < s) red[tid] = fmaxf(red[tid], red[tid+s]);
        __syncthreads();
    }
    m = red[0]; __syncthreads();

    float sum = 0.f;
    for (int t = tid; t < NT; t += 256)
        if (t < len) {
            float e = (e0[t] + e0[MROWS + t]) + (e0[2*MROWS + t] + e0[3*MROWS + t]);
            sum += expf(2.f * e - m);
        }
    red[tid] = sum; __syncthreads();
    for (int s = 128; s > 0; s >>= 1) {
        if (tid < s) red[tid] += red[tid+s];
        __syncthreads();
    }
    float inv = 1.f / red[0];

    if (tid < 80) {
        int t = t0 + tid;
        float v = 0.f;
        if (t < len) {
            float e = (e0[t] + e0[MROWS + t]) + (e0[2*MROWS + t] + e0[3*MROWS + t]);
            v = expf(2.f * e - m) * inv;
        }
        aw[tid] = v;
        if (write_attn) attn_dst[b*NT + t] = v;
    }
    __syncthreads();

    // ctx accumulate: 80 rows, 8 per iteration (MLP 8), fp16 enc reads
    int d0 = tid * 4;
    float a0 = 0.f, a1 = 0.f, a2 = 0.f, a3 = 0.f;
    const __half* base = g_Ah + (size_t)b * NT * KEXT + d0;
    #pragma unroll 1
    for (int i = 0; i < 10; i++) {
        int t = t0 + i * 8;
        uint2 v[8];
        #pragma unroll
        for (int r = 0; r < 8; r++)
            v[r] = *reinterpret_cast<const uint2*>(base + (size_t)(t + r) * KEXT);
        #pragma unroll
        for (int r = 0; r < 8; r++) {
            float w = aw[i * 8 + r];
            float2 p = __half22float2(*reinterpret_cast<__half2*>(&v[r].x));
            float2 q = __half22float2(*reinterpret_cast<__half2*>(&v[r].y));
            a0 = fmaf(w, p.x, a0); a1 = fmaf(w, p.y, a1);
            a2 = fmaf(w, q.x, a2); a3 = fmaf(w, q.y, a3);
        }
    }
    atomicAdd(&g_ctx[b*ED + d0 + 0], a0);
    atomicAdd(&g_ctx[b*ED + d0 + 1], a1);
    atomicAdd(&g_ctx[b*ED + d0 + 2], a2);
    atomicAdd(&g_ctx[b*ED + d0 + 3], a3);
}

// ---------------------------------------------------------------------------
// out: grid (4 bgroup, 16 ogroup), block 256 = 64 o-cols x 4 d-slices.
// c[b,o] = ctx[b]@W_o + b_o for 8 b's per block (W_o traffic 4MB x 4).
// ---------------------------------------------------------------------------
__global__ void out_kernel(const float* __restrict__ W_o,
                           const float* __restrict__ b_o,
                           float* __restrict__ c_dst, int write_c) {
    __shared__ float cs[8][ED];        // 32KB
    __shared__ float red[4][64][8];    // 8KB
    if (!write_c) return;
    const int tid = threadIdx.x;
    const int bg = blockIdx.x;
    const int ol = tid & 63;
    const int o = blockIdx.y * 64 + ol;
    const int sl = tid >> 6;

    for (int i = tid; i < 2048; i += 256)
        reinterpret_cast<float4*>(&cs[0][0])[i] =
            reinterpret_cast<const float4*>(g_ctx + (size_t)bg * 8 * ED)[i];
    __syncthreads();

    float acc[8];
    #pragma unroll
    for (int j = 0; j < 8; j++) acc[j] = 0.f;
    #pragma unroll 1
    for (int dd = 0; dd < 256; dd += 8) {
        int d = sl * 256 + dd;
        float w[8];
        #pragma unroll
        for (int u = 0; u < 8; u++) w[u] = W_o[(d + u) * OD + o];
        #pragma unroll
        for (int j = 0; j < 8; j++)
            #pragma unroll
            for (int u = 0; u < 8; u++)
                acc[j] = fmaf(cs[j][d + u], w[u], acc[j]);
    }
    #pragma unroll
    for (int j = 0; j < 8; j++) red[sl][ol][j] = acc[j];
    __syncthreads();
    if (sl == 0) {
        float base = b_o[o];
        #pragma unroll
        for (int j = 0; j < 8; j++)
            c_dst[(bg * 8 + j) * OD + o] =
                base + (red[0][ol][j] + red[1][ol][j]) + (red[2][ol][j] + red[3][ol][j]);
    }
}

// ---------------------------------------------------------------------------
extern "C" void kernel_launch(void* const* d_in, const int* in_sizes, int n_in,
                              void* d_out, int out_size) {
    const float* enc_pad  = (const float*)d_in[0];
    const int*   enc_len  = (const int*)  d_in[1];
    const float* dec_h    = (const float*)d_in[2];
    const float* att_prev = (const float*)d_in[3];
    const float* W_enc    = (const float*)d_in[4];
    const float* b_enc    = (const float*)d_in[5];
    const float* W_dec    = (const float*)d_in[6];
    const float* b_dec    = (const float*)d_in[7];
    const float* W_att    = (const float*)d_in[8];
    const float* b_att    = (const float*)d_in[9];
    const float* conv_w   = (const float*)d_in[10];
    const float* gvec     = (const float*)d_in[11];
    const float* W_o      = (const float*)d_in[12];
    const float* b_o      = (const float*)d_in[13];

    float* out = (float*)d_out;
    float* c_dst    = out;
    float* attn_dst = out;
    int write_c = 0, write_attn = 0;
    if (out_size >= NB*OD + NB*NT) {
        c_dst = out; attn_dst = out + NB*OD;
        write_c = 1; write_attn = 1;
    } else if (out_size == NB*NT) {
        attn_dst = out; write_attn = 1;
    } else {
        c_dst = out; write_c = 1;
    }

    static int smem_set = 0;
    if (!smem_set) {
        cudaFuncSetAttribute(gemm_e_mma, cudaFuncAttributeMaxDynamicSharedMemorySize, DYN_SMEM);
        smem_set = 1;
    }

    prep_A<<<2256, 256>>>(enc_pad, att_prev, conv_w, enc_len);
    btrans_kernel<<<dim3(KEXT/32, AD/32), dim3(32,32)>>>(W_enc, W_att);
    bias_kernel<<<dim3(4, 8), 256>>>(dec_h, W_dec, b_dec, b_enc, b_att);
    gemm_e_mma<<<dim3(4, 500), 256, DYN_SMEM>>>(gvec, enc_len);
    ctx_fused<<<dim3(NB, 25), 256>>>(enc_len, attn_dst, write_attn);
    out_kernel<<<dim3(4, 16), 256>>>(W_o, b_o, c_dst, write_c);
}

// round 13
// speedup vs baseline: 2.1803x; 1.1003x over previous
#include <cuda_runtime.h>
#include <cuda_fp16.h>
#include <cstdint>
#include <math.h>

#define NB 32
#define NT 2000
#define ED 1024
#define AD 512
#define CCH 32
#define KHALF 50
#define KW 101
#define OD 1024
#define MROWS (NB*NT)     /* 64000 */
#define KEXT (ED + CCH)   /* 1056 */

// ---------------- device scratch (zero-initialized device globals) ----------
__device__ __align__(128) __half g_Ah[(size_t)MROWS * KEXT];  // enc || conv, fp16
__device__ __align__(128) __half g_Bth[AD * KEXT];            // [n][k] fp16
__device__ float g_bias[NB * AD];
__device__ float g_e4[4 * MROWS];                             // per-Nblock partial e
__device__ float g_ctx[NB * ED];

// ---------------- helpers ----------------
__device__ __forceinline__ void cp16(uint32_t dst, const void* src) {
    asm volatile("cp.async.cg.shared.global [%0], [%1], 16;" :: "r"(dst), "l"(src) : "memory");
}
__device__ __forceinline__ uint32_t smem_u32(const void* p) {
    uint32_t a;
    asm("{ .reg .u64 t; cvta.to.shared.u64 t, %1; cvt.u32.u64 %0, t; }" : "=r"(a) : "l"(p));
    return a;
}
__device__ __forceinline__ uint32_t h2u(__half2 h) {
    return *reinterpret_cast<uint32_t*>(&h);
}
__device__ __forceinline__ float fast_tanh(float x) {
    float y; asm("tanh.approx.f32 %0, %1;" : "=f"(y) : "f"(x)); return y;
}
__device__ __forceinline__ void ldmx4(uint32_t& r0, uint32_t& r1, uint32_t& r2, uint32_t& r3,
                                      uint32_t addr) {
    asm volatile("ldmatrix.sync.aligned.m8n8.x4.shared.b16 {%0,%1,%2,%3}, [%4];"
                 : "=r"(r0), "=r"(r1), "=r"(r2), "=r"(r3) : "r"(addr));
}
__device__ __forceinline__ void mma_f16(float& d0, float& d1, float& d2, float& d3,
                                        uint32_t a0, uint32_t a1, uint32_t a2, uint32_t a3,
                                        uint32_t b0, uint32_t b1) {
    asm volatile(
        "mma.sync.aligned.m16n8k16.row.col.f32.f16.f16.f32 "
        "{%0,%1,%2,%3},{%4,%5,%6,%7},{%8,%9},{%0,%1,%2,%3};"
        : "+f"(d0), "+f"(d1), "+f"(d2), "+f"(d3)
        : "r"(a0), "r"(a1), "r"(a2), "r"(a3), "r"(b0), "r"(b1));
}

// ---------------------------------------------------------------------------
// prep_all2: ONE lean grid (2800 blocks x 256 thr, 16KB DYNAMIC smem):
//   [0,2000)    enc -> fp16 g_Ah cols 0..1023 (no smem, streaming; mask-skip)
//   [2000,2256) location conv -> g_Ah cols 1024..1055 (14.3KB smem; mask-skip)
//   [2256,2784) B' transpose -> g_Bth fp16 (4.2KB smem)
//   [2784,2800) bias (4 batches/block, 16KB smem) + zero g_ctx
// Resource discipline (R8 lesson): dynamic smem only, no branch > ~56 regs,
// so streaming blocks stay thread-limited (8 CTA/SM), not resource-limited.
// ---------------------------------------------------------------------------
__global__ __launch_bounds__(256)
void prep_all2(const float* __restrict__ enc,
               const float* __restrict__ att_prev,
               const float* __restrict__ conv_w,
               const int* __restrict__ enc_len,
               const float* __restrict__ W_enc,
               const float* __restrict__ W_att,
               const float* __restrict__ dec_h,
               const float* __restrict__ W_dec,
               const float* __restrict__ b_dec,
               const float* __restrict__ b_enc,
               const float* __restrict__ b_att) {
    extern __shared__ float dynf[];
    const int tid = threadIdx.x;
    const int bid = blockIdx.x;

    if (bid < 2000) {
        // ---- enc fp16 convert: 32 rows per block, no smem ----
        const int r0 = bid * 32;
        const int b0 = r0 / NT, b1 = (r0 + 31) / NT;
        if (b0 == b1 && (r0 - b0 * NT) >= __ldg(&enc_len[b0])) return;
        #pragma unroll 4
        for (int q = 0; q < 32; q++) {
            int row = q, c4 = tid;
            float4 v = *reinterpret_cast<const float4*>(enc + (size_t)(r0 + row) * ED + c4 * 4);
            uint2 pk = make_uint2(h2u(__floats2half2_rn(v.x, v.y)),
                                  h2u(__floats2half2_rn(v.z, v.w)));
            *reinterpret_cast<uint2*>(g_Ah + (size_t)(r0 + row) * KEXT + c4 * 4) = pk;
        }
    } else if (bid < 2256) {
        // ---- location conv: ap[350] + wk[3232] in dynamic smem ----
        float* ap = dynf;
        float* wk = dynf + 352;
        int idx = bid - 2000;
        int b = idx >> 3;
        int t0 = (idx & 7) * 250;
        if (t0 >= __ldg(&enc_len[b])) return;
        for (int i = tid; i < 350; i += 256) {
            int gpos = t0 - KHALF + i;
            ap[i] = (gpos >= 0 && gpos < NT) ? att_prev[b * NT + gpos] : 0.f;
        }
        for (int i = tid; i < CCH * KW; i += 256) wk[i] = conv_w[i];
        __syncthreads();
        if (tid < 250) {
            float s[CCH];
            #pragma unroll
            for (int c = 0; c < CCH; c++) s[c] = 0.f;
            for (int k = 0; k < KW; k++) {
                float av = ap[tid + k];
                #pragma unroll
                for (int c = 0; c < CCH; c++) s[c] = fmaf(av, wk[c * KW + k], s[c]);
            }
            uint32_t u32[16];
            #pragma unroll
            for (int k = 0; k < 16; k++) u32[k] = h2u(__floats2half2_rn(s[2*k], s[2*k+1]));
            uint4* dst = reinterpret_cast<uint4*>(g_Ah + (size_t)(b * NT + t0 + tid) * KEXT + ED);
            dst[0] = make_uint4(u32[0], u32[1], u32[2], u32[3]);
            dst[1] = make_uint4(u32[4], u32[5], u32[6], u32[7]);
            dst[2] = make_uint4(u32[8], u32[9], u32[10], u32[11]);
            dst[3] = make_uint4(u32[12], u32[13], u32[14], u32[15]);
        }
    } else if (bid < 2784) {
        // ---- B transpose -> fp16 K-major: sm[32][33] in dynamic smem ----
        float* sm = dynf;
        int idx = bid - 2256;
        int kb = idx % 33, nb = idx / 33;
        int tx = tid & 31, ty8 = tid >> 5;
        #pragma unroll
        for (int r = ty8; r < 32; r += 8) {
            int k = kb * 32 + r;
            int n = nb * 32 + tx;
            sm[r * 33 + tx] = (k < ED) ? W_enc[k * AD + n] : W_att[(k - ED) * AD + n];
        }
        __syncthreads();
        #pragma unroll
        for (int r = ty8; r < 32; r += 8)
            g_Bth[(size_t)(nb * 32 + r) * KEXT + kb * 32 + tx] =
                __float2half_rn(sm[tx * 33 + r]);
    } else {
        // ---- bias: 4 batches per block; ds[4][1024] in dynamic smem ----
        float* ds = dynf;                 // 16KB
        int idx = bid - 2784;             // 0..15
        int bg = idx >> 1;                // 0..7 (4 b's each)
        int half = idx & 1;
        int a = half * 256 + tid;
        for (int i = tid; i < 1024; i += 256)
            reinterpret_cast<float4*>(ds)[i] =
                reinterpret_cast<const float4*>(dec_h + (size_t)bg * 4 * ED)[i];
        // zero g_ctx: 16 blocks x 2048 floats
        for (int i = tid; i < 2048; i += 256) g_ctx[idx * 2048 + i] = 0.f;
        __syncthreads();
        float acc0 = 0.f, acc1 = 0.f, acc2 = 0.f, acc3 = 0.f;
        #pragma unroll 8
        for (int d = 0; d < ED; d++) {
            float w = W_dec[d * AD + a];
            acc0 = fmaf(ds[d], w, acc0);
            acc1 = fmaf(ds[ED + d], w, acc1);
            acc2 = fmaf(ds[2*ED + d], w, acc2);
            acc3 = fmaf(ds[3*ED + d], w, acc3);
        }
        float base = b_dec[a] + b_enc[a] + b_att[a];
        g_bias[(bg * 4 + 0) * AD + a] = base + acc0;
        g_bias[(bg * 4 + 1) * AD + a] = base + acc1;
        g_bias[(bg * 4 + 2) * AD + a] = base + acc2;
        g_bias[(bg * 4 + 3) * AD + a] = base + acc3;
    }
}

// ---------------------------------------------------------------------------
// Main GEMM (mma.sync fp16 m16n8k16 + ldmatrix), masked-CTA early exit.
// [at legacy-HMMA rt16 ceiling: ~181us, do not touch]
// ---------------------------------------------------------------------------
#define PITCH 80
#define STAGE 20480            /* A 10240 + B 10240 */
#define DYN_SMEM (3*STAGE)

__global__ __launch_bounds__(256, 2)
void gemm_e_mma(const float* __restrict__ gv, const int* __restrict__ enc_len) {
    extern __shared__ char dyn[];
    __shared__ float gS[128];
    __shared__ float biasS[2][128];
    __shared__ float e_buf[4][128];

    const int tid = threadIdx.x, lane = tid & 31, wid = tid >> 5;
    const int wm = wid >> 2, wn = wid & 3;
    const int g = lane >> 2, c4 = lane & 3;
    const int n0 = blockIdx.x * 128;
    const int m0 = blockIdx.y * 128;
    const int bA = m0 / NT, bB = (m0 + 127) / NT;
    if (bA == bB && (m0 - bA * NT) >= __ldg(&enc_len[bA])) return;

    const uint32_t sbase = smem_u32(dyn);

    if (tid < 128) {
        gS[tid] = gv[n0 + tid];
        biasS[0][tid] = g_bias[bA*AD + n0 + tid];
    } else {
        biasS[1][tid-128] = g_bias[bB*AD + n0 + tid - 128];
    }

    const uint32_t aOff = (uint32_t)((wm*64 + (lane & 15)) * PITCH + ((lane >> 4) & 1) * 16);
    const uint32_t bOff = 10240u +
        (uint32_t)((wn*32 + (lane & 7) + ((lane >> 4) & 1) * 8) * PITCH + ((lane >> 3) & 1) * 16);
    uint32_t aAddr[3], bAddr[3];
    #pragma unroll
    for (int s = 0; s < 3; s++) {
        aAddr[s] = sbase + s*STAGE + aOff;
        bAddr[s] = sbase + s*STAGE + bOff;
    }

    float d[4][4][4];
    #pragma unroll
    for (int i = 0; i < 4; i++)
        #pragma unroll
        for (int jx = 0; jx < 4; jx++)
            #pragma unroll
            for (int qx = 0; qx < 4; qx++) d[i][jx][qx] = 0.f;

    auto issue_tile = [&](int i, int s) {
        uint32_t stA = sbase + s * STAGE;
        uint32_t stB = stA + 10240;
        #pragma unroll
        for (int q = 0; q < 2; q++) {
            int u = q * 256 + tid;           // 0..511
            int row = u >> 2, c16 = u & 3;
            cp16(stA + row * PITCH + c16 * 16,
                 g_Ah + (size_t)(m0 + row) * KEXT + i * 32 + c16 * 8);
            cp16(stB + row * PITCH + c16 * 16,
                 g_Bth + (size_t)(n0 + row) * KEXT + i * 32 + c16 * 8);
        }
        asm volatile("cp.async.commit_group;" ::: "memory");
    };

    issue_tile(0, 0);
    issue_tile(1, 1);

    int st = 0;
    for (int i = 0; i < 33; i++) {
        if (i < 32) asm volatile("cp.async.wait_group 1;" ::: "memory");
        else        asm volatile("cp.async.wait_group 0;" ::: "memory");
        __syncthreads();
        if (i + 2 <= 32) {
            int s2 = st + 2; if (s2 >= 3) s2 -= 3;
            issue_tile(i + 2, s2);
        }

        const uint32_t aS = aAddr[st], bS = bAddr[st];
        #pragma unroll
        for (int ks = 0; ks < 2; ks++) {
            uint32_t br[4][2];
            ldmx4(br[0][0], br[0][1], br[1][0], br[1][1], bS + ks*32);
            ldmx4(br[2][0], br[2][1], br[3][0], br[3][1], bS + 16*PITCH + ks*32);
            #pragma unroll
            for (int mf = 0; mf < 4; mf++) {
                uint32_t a0, a1, a2, a3;
                ldmx4(a0, a1, a2, a3, aS + mf*16*PITCH + ks*32);
                #pragma unroll
                for (int nf = 0; nf < 4; nf++)
                    mma_f16(d[mf][nf][0], d[mf][nf][1], d[mf][nf][2], d[mf][nf][3],
                            a0, a1, a2, a3, br[nf][0], br[nf][1]);
            }
        }
        if (++st == 3) st = 0;
    }

    // ---- epilogue: tanh + g-dot, reduce to e-partial ----
    float pr[4][2];
    #pragma unroll
    for (int mf = 0; mf < 4; mf++) { pr[mf][0] = 0.f; pr[mf][1] = 0.f; }

    #pragma unroll
    for (int mf = 0; mf < 4; mf++) {
        int r_lo = wm * 64 + mf * 16 + g;
        int bi_lo = ((m0 + r_lo) / NT == bA) ? 0 : 1;
        int bi_hi = ((m0 + r_lo + 8) / NT == bA) ? 0 : 1;
        #pragma unroll
        for (int nf = 0; nf < 4; nf++) {
            #pragma unroll
            for (int jx = 0; jx < 4; jx++) {
                int colL = wn * 32 + nf * 8 + 2 * c4 + (jx & 1);
                int bi = (jx >= 2) ? bi_hi : bi_lo;
                float v = d[mf][nf][jx] + biasS[bi][colL];
                pr[mf][jx >= 2] = fmaf(fast_tanh(v), gS[colL], pr[mf][jx >= 2]);
            }
        }
    }
    #pragma unroll
    for (int mf = 0; mf < 4; mf++) {
        #pragma unroll
        for (int h = 0; h < 2; h++) {
            pr[mf][h] += __shfl_xor_sync(0xffffffffu, pr[mf][h], 1);
            pr[mf][h] += __shfl_xor_sync(0xffffffffu, pr[mf][h], 2);
        }
    }
    if (c4 == 0) {
        #pragma unroll
        for (int mf = 0; mf < 4; mf++) {
            e_buf[wn][wm * 64 + mf * 16 + g]     = pr[mf][0];
            e_buf[wn][wm * 64 + mf * 16 + g + 8] = pr[mf][1];
        }
    }
    __syncthreads();
    if (tid < 128)
        g_e4[blockIdx.x * MROWS + m0 + tid] =
            (e_buf[0][tid] + e_buf[1][tid]) + (e_buf[2][tid] + e_buf[3][tid]);
}

// ---------------------------------------------------------------------------
// ctx_fused: per (b, chunk of 80 t): recompute row softmax stats from g_e4,
// emit attn for own chunk, then ctx partial accumulation.
// ---------------------------------------------------------------------------
__global__ void ctx_fused(const int* __restrict__ enc_len,
                          float* __restrict__ attn_dst, int write_attn) {
    __shared__ float red[256];
    __shared__ float aw[80];
    const int b = blockIdx.x, chunk = blockIdx.y;
    const int len = enc_len[b];
    const int t0 = chunk * 80;
    const int tid = threadIdx.x;

    if (t0 >= len) {            // fully masked: attn zeros only
        if (write_attn && tid < 80) attn_dst[b*NT + t0 + tid] = 0.f;
        return;
    }
    const float* e0 = g_e4 + b * NT;

    float m = -1e30f;
    for (int t = tid; t < NT; t += 256)
        if (t < len) {
            float e = (e0[t] + e0[MROWS + t]) + (e0[2*MROWS + t] + e0[3*MROWS + t]);
            m = fmaxf(m, 2.f * e);
        }
    red[tid] = m; __syncthreads();
    for (int s = 128; s > 0; s >>= 1) {
        if (tid < s) red[tid] = fmaxf(red[tid], red[tid+s]);
        __syncthreads();
    }
    m = red[0]; __syncthreads();

    float sum = 0.f;
    for (int t = tid; t < NT; t += 256)
        if (t < len) {
            float e = (e0[t] + e0[MROWS + t]) + (e0[2*MROWS + t] + e0[3*MROWS + t]);
            sum += expf(2.f * e - m);
        }
    red[tid] = sum; __syncthreads();
    for (int s = 128; s > 0; s >>= 1) {
        if (tid < s) red[tid] += red[tid+s];
        __syncthreads();
    }
    float inv = 1.f / red[0];

    if (tid < 80) {
        int t = t0 + tid;
        float v = 0.f;
        if (t < len) {
            float e = (e0[t] + e0[MROWS + t]) + (e0[2*MROWS + t] + e0[3*MROWS + t]);
            v = expf(2.f * e - m) * inv;
        }
        aw[tid] = v;
        if (write_attn) attn_dst[b*NT + t] = v;
    }
    __syncthreads();

    // ctx accumulate: 80 rows, 8 per iteration (MLP 8), fp16 enc reads
    int d0 = tid * 4;
    float a0 = 0.f, a1 = 0.f, a2 = 0.f, a3 = 0.f;
    const __half* base = g_Ah + (size_t)b * NT * KEXT + d0;
    #pragma unroll 1
    for (int i = 0; i < 10; i++) {
        int t = t0 + i * 8;
        uint2 v[8];
        #pragma unroll
        for (int r = 0; r < 8; r++)
            v[r] = *reinterpret_cast<const uint2*>(base + (size_t)(t + r) * KEXT);
        #pragma unroll
        for (int r = 0; r < 8; r++) {
            float w = aw[i * 8 + r];
            float2 p = __half22float2(*reinterpret_cast<__half2*>(&v[r].x));
            float2 q = __half22float2(*reinterpret_cast<__half2*>(&v[r].y));
            a0 = fmaf(w, p.x, a0); a1 = fmaf(w, p.y, a1);
            a2 = fmaf(w, q.x, a2); a3 = fmaf(w, q.y, a3);
        }
    }
    atomicAdd(&g_ctx[b*ED + d0 + 0], a0);
    atomicAdd(&g_ctx[b*ED + d0 + 1], a1);
    atomicAdd(&g_ctx[b*ED + d0 + 2], a2);
    atomicAdd(&g_ctx[b*ED + d0 + 3], a3);
}

// ---------------------------------------------------------------------------
// out: grid (4 bgroup, 16 ogroup), block 256 = 64 o-cols x 4 d-slices.
// c[b,o] = ctx[b]@W_o + b_o for 8 b's per block.
// ---------------------------------------------------------------------------
__global__ void out_kernel(const float* __restrict__ W_o,
                           const float* __restrict__ b_o,
                           float* __restrict__ c_dst, int write_c) {
    __shared__ float cs[8][ED];        // 32KB
    __shared__ float red[4][64][8];    // 8KB
    if (!write_c) return;
    const int tid = threadIdx.x;
    const int bg = blockIdx.x;
    const int ol = tid & 63;
    const int o = blockIdx.y * 64 + ol;
    const int sl = tid >> 6;

    for (int i = tid; i < 2048; i += 256)
        reinterpret_cast<float4*>(&cs[0][0])[i] =
            reinterpret_cast<const float4*>(g_ctx + (size_t)bg * 8 * ED)[i];
    __syncthreads();

    float acc[8];
    #pragma unroll
    for (int j = 0; j < 8; j++) acc[j] = 0.f;
    #pragma unroll 1
    for (int dd = 0; dd < 256; dd += 8) {
        int d = sl * 256 + dd;
        float w[8];
        #pragma unroll
        for (int u = 0; u < 8; u++) w[u] = W_o[(d + u) * OD + o];
        #pragma unroll
        for (int j = 0; j < 8; j++)
            #pragma unroll
            for (int u = 0; u < 8; u++)
                acc[j] = fmaf(cs[j][d + u], w[u], acc[j]);
    }
    #pragma unroll
    for (int j = 0; j < 8; j++) red[sl][ol][j] = acc[j];
    __syncthreads();
    if (sl == 0) {
        float base = b_o[o];
        #pragma unroll
        for (int j = 0; j < 8; j++)
            c_dst[(bg * 8 + j) * OD + o] =
                base + (red[0][ol][j] + red[1][ol][j]) + (red[2][ol][j] + red[3][ol][j]);
    }
}

// ---------------------------------------------------------------------------
extern "C" void kernel_launch(void* const* d_in, const int* in_sizes, int n_in,
                              void* d_out, int out_size) {
    const float* enc_pad  = (const float*)d_in[0];
    const int*   enc_len  = (const int*)  d_in[1];
    const float* dec_h    = (const float*)d_in[2];
    const float* att_prev = (const float*)d_in[3];
    const float* W_enc    = (const float*)d_in[4];
    const float* b_enc    = (const float*)d_in[5];
    const float* W_dec    = (const float*)d_in[6];
    const float* b_dec    = (const float*)d_in[7];
    const float* W_att    = (const float*)d_in[8];
    const float* b_att    = (const float*)d_in[9];
    const float* conv_w   = (const float*)d_in[10];
    const float* gvec     = (const float*)d_in[11];
    const float* W_o      = (const float*)d_in[12];
    const float* b_o      = (const float*)d_in[13];

    float* out = (float*)d_out;
    float* c_dst    = out;
    float* attn_dst = out;
    int write_c = 0, write_attn = 0;
    if (out_size >= NB*OD + NB*NT) {
        c_dst = out; attn_dst = out + NB*OD;
        write_c = 1; write_attn = 1;
    } else if (out_size == NB*NT) {
        attn_dst = out; write_attn = 1;
    } else {
        c_dst = out; write_c = 1;
    }

    static int smem_set = 0;
    if (!smem_set) {
        cudaFuncSetAttribute(gemm_e_mma, cudaFuncAttributeMaxDynamicSharedMemorySize, DYN_SMEM);
        smem_set = 1;
    }

    prep_all2<<<2800, 256, 16384>>>(enc_pad, att_prev, conv_w, enc_len,
                                    W_enc, W_att, dec_h, W_dec, b_dec, b_enc, b_att);
    gemm_e_mma<<<dim3(4, 500), 256, DYN_SMEM>>>(gvec, enc_len);
    ctx_fused<<<dim3(NB, 25), 256>>>(enc_len, attn_dst, write_attn);
    out_kernel<<<dim3(4, 16), 256>>>(W_o, b_o, c_dst, write_c);
}

// round 15
// speedup vs baseline: 2.2663x; 1.0395x over previous
#include <cuda_runtime.h>
#include <cuda_fp16.h>
#include <cstdint>
#include <math.h>

#define NB 32
#define NT 2000
#define ED 1024
#define AD 512
#define CCH 32
#define KHALF 50
#define KW 101
#define OD 1024
#define MROWS (NB*NT)     /* 64000 */
#define KEXT (ED + CCH)   /* 1056 */

// ---------------- device scratch (zero-initialized device globals) ----------
__device__ __align__(128) __half g_Ah[(size_t)MROWS * KEXT];  // enc || conv, fp16
__device__ __align__(128) __half g_Bth[AD * KEXT];            // [n][k] fp16
__device__ float g_bias[NB * AD];
__device__ float g_e4[4 * MROWS];                             // per-Nblock partial e
__device__ float g_ctx[NB * ED];

// ---------------- helpers ----------------
__device__ __forceinline__ void cp16(uint32_t dst, const void* src) {
    asm volatile("cp.async.cg.shared.global [%0], [%1], 16;" :: "r"(dst), "l"(src) : "memory");
}
__device__ __forceinline__ uint32_t smem_u32(const void* p) {
    uint32_t a;
    asm("{ .reg .u64 t; cvta.to.shared.u64 t, %1; cvt.u32.u64 %0, t; }" : "=r"(a) : "l"(p));
    return a;
}
__device__ __forceinline__ uint32_t h2u(__half2 h) {
    return *reinterpret_cast<uint32_t*>(&h);
}
__device__ __forceinline__ float fast_tanh(float x) {
    float y; asm("tanh.approx.f32 %0, %1;" : "=f"(y) : "f"(x)); return y;
}
__device__ __forceinline__ void ldmx4(uint32_t& r0, uint32_t& r1, uint32_t& r2, uint32_t& r3,
                                      uint32_t addr) {
    asm volatile("ldmatrix.sync.aligned.m8n8.x4.shared.b16 {%0,%1,%2,%3}, [%4];"
                 : "=r"(r0), "=r"(r1), "=r"(r2), "=r"(r3) : "r"(addr));
}
__device__ __forceinline__ void mma_f16(float& d0, float& d1, float& d2, float& d3,
                                        uint32_t a0, uint32_t a1, uint32_t a2, uint32_t a3,
                                        uint32_t b0, uint32_t b1) {
    asm volatile(
        "mma.sync.aligned.m16n8k16.row.col.f32.f16.f16.f32 "
        "{%0,%1,%2,%3},{%4,%5,%6,%7},{%8,%9},{%0,%1,%2,%3};"
        : "+f"(d0), "+f"(d1), "+f"(d2), "+f"(d3)
        : "r"(a0), "r"(a1), "r"(a2), "r"(a3), "r"(b0), "r"(b1));
}

// ---------------------------------------------------------------------------
// prep_all2: ONE lean grid (2800 blocks x 256 thr, 16KB DYNAMIC smem):
//   [0,2000)    enc -> fp16 g_Ah cols 0..1023 (no smem, streaming; mask-skip)
//   [2000,2256) location conv -> g_Ah cols 1024..1055 (14.3KB smem; mask-skip)
//   [2256,2784) B' transpose -> g_Bth fp16 (4.2KB smem)
//   [2784,2800) bias (4 batches/block, 16KB smem) + zero g_ctx
// ---------------------------------------------------------------------------
__global__ __launch_bounds__(256)
void prep_all2(const float* __restrict__ enc,
               const float* __restrict__ att_prev,
               const float* __restrict__ conv_w,
               const int* __restrict__ enc_len,
               const float* __restrict__ W_enc,
               const float* __restrict__ W_att,
               const float* __restrict__ dec_h,
               const float* __restrict__ W_dec,
               const float* __restrict__ b_dec,
               const float* __restrict__ b_enc,
               const float* __restrict__ b_att) {
    extern __shared__ float dynf[];
    const int tid = threadIdx.x;
    const int bid = blockIdx.x;

    if (bid < 2000) {
        const int r0 = bid * 32;
        const int b0 = r0 / NT, b1 = (r0 + 31) / NT;
        if (b0 == b1 && (r0 - b0 * NT) >= __ldg(&enc_len[b0])) return;
        #pragma unroll 4
        for (int q = 0; q < 32; q++) {
            int row = q, c4 = tid;
            float4 v = *reinterpret_cast<const float4*>(enc + (size_t)(r0 + row) * ED + c4 * 4);
            uint2 pk = make_uint2(h2u(__floats2half2_rn(v.x, v.y)),
                                  h2u(__floats2half2_rn(v.z, v.w)));
            *reinterpret_cast<uint2*>(g_Ah + (size_t)(r0 + row) * KEXT + c4 * 4) = pk;
        }
    } else if (bid < 2256) {
        float* ap = dynf;
        float* wk = dynf + 352;
        int idx = bid - 2000;
        int b = idx >> 3;
        int t0 = (idx & 7) * 250;
        if (t0 >= __ldg(&enc_len[b])) return;
        for (int i = tid; i < 350; i += 256) {
            int gpos = t0 - KHALF + i;
            ap[i] = (gpos >= 0 && gpos < NT) ? att_prev[b * NT + gpos] : 0.f;
        }
        for (int i = tid; i < CCH * KW; i += 256) wk[i] = conv_w[i];
        __syncthreads();
        if (tid < 250) {
            float s[CCH];
            #pragma unroll
            for (int c = 0; c < CCH; c++) s[c] = 0.f;
            for (int k = 0; k < KW; k++) {
                float av = ap[tid + k];
                #pragma unroll
                for (int c = 0; c < CCH; c++) s[c] = fmaf(av, wk[c * KW + k], s[c]);
            }
            uint32_t u32[16];
            #pragma unroll
            for (int k = 0; k < 16; k++) u32[k] = h2u(__floats2half2_rn(s[2*k], s[2*k+1]));
            uint4* dst = reinterpret_cast<uint4*>(g_Ah + (size_t)(b * NT + t0 + tid) * KEXT + ED);
            dst[0] = make_uint4(u32[0], u32[1], u32[2], u32[3]);
            dst[1] = make_uint4(u32[4], u32[5], u32[6], u32[7]);
            dst[2] = make_uint4(u32[8], u32[9], u32[10], u32[11]);
            dst[3] = make_uint4(u32[12], u32[13], u32[14], u32[15]);
        }
    } else if (bid < 2784) {
        float* sm = dynf;
        int idx = bid - 2256;
        int kb = idx % 33, nb = idx / 33;
        int tx = tid & 31, ty8 = tid >> 5;
        #pragma unroll
        for (int r = ty8; r < 32; r += 8) {
            int k = kb * 32 + r;
            int n = nb * 32 + tx;
            sm[r * 33 + tx] = (k < ED) ? W_enc[k * AD + n] : W_att[(k - ED) * AD + n];
        }
        __syncthreads();
        #pragma unroll
        for (int r = ty8; r < 32; r += 8)
            g_Bth[(size_t)(nb * 32 + r) * KEXT + kb * 32 + tx] =
                __float2half_rn(sm[tx * 33 + r]);
    } else {
        float* ds = dynf;                 // 16KB
        int idx = bid - 2784;             // 0..15
        int bg = idx >> 1;                // 0..7 (4 b's each)
        int half = idx & 1;
        int a = half * 256 + tid;
        for (int i = tid; i < 1024; i += 256)
            reinterpret_cast<float4*>(ds)[i] =
                reinterpret_cast<const float4*>(dec_h + (size_t)bg * 4 * ED)[i];
        for (int i = tid; i < 2048; i += 256) g_ctx[idx * 2048 + i] = 0.f;
        __syncthreads();
        float acc0 = 0.f, acc1 = 0.f, acc2 = 0.f, acc3 = 0.f;
        #pragma unroll 8
        for (int d = 0; d < ED; d++) {
            float w = W_dec[d * AD + a];
            acc0 = fmaf(ds[d], w, acc0);
            acc1 = fmaf(ds[ED + d], w, acc1);
            acc2 = fmaf(ds[2*ED + d], w, acc2);
            acc3 = fmaf(ds[3*ED + d], w, acc3);
        }
        float base = b_dec[a] + b_enc[a] + b_att[a];
        g_bias[(bg * 4 + 0) * AD + a] = base + acc0;
        g_bias[(bg * 4 + 1) * AD + a] = base + acc1;
        g_bias[(bg * 4 + 2) * AD + a] = base + acc2;
        g_bias[(bg * 4 + 3) * AD + a] = base + acc3;
    }
}

// ---------------------------------------------------------------------------
// Main GEMM (mma.sync fp16 m16n8k16 + ldmatrix), masked-CTA early exit.
// [at legacy-HMMA rt16 ceiling: ~181us, do not touch]
// ---------------------------------------------------------------------------
#define PITCH 80
#define STAGE 20480            /* A 10240 + B 10240 */
#define DYN_SMEM (3*STAGE)

__global__ __launch_bounds__(256, 2)
void gemm_e_mma(const float* __restrict__ gv, const int* __restrict__ enc_len) {
    extern __shared__ char dyn[];
    __shared__ float gS[128];
    __shared__ float biasS[2][128];
    __shared__ float e_buf[4][128];

    const int tid = threadIdx.x, lane = tid & 31, wid = tid >> 5;
    const int wm = wid >> 2, wn = wid & 3;
    const int g = lane >> 2, c4 = lane & 3;
    const int n0 = blockIdx.x * 128;
    const int m0 = blockIdx.y * 128;
    const int bA = m0 / NT, bB = (m0 + 127) / NT;
    if (bA == bB && (m0 - bA * NT) >= __ldg(&enc_len[bA])) return;

    const uint32_t sbase = smem_u32(dyn);

    if (tid < 128) {
        gS[tid] = gv[n0 + tid];
        biasS[0][tid] = g_bias[bA*AD + n0 + tid];
    } else {
        biasS[1][tid-128] = g_bias[bB*AD + n0 + tid - 128];
    }

    const uint32_t aOff = (uint32_t)((wm*64 + (lane & 15)) * PITCH + ((lane >> 4) & 1) * 16);
    const uint32_t bOff = 10240u +
        (uint32_t)((wn*32 + (lane & 7) + ((lane >> 4) & 1) * 8) * PITCH + ((lane >> 3) & 1) * 16);
    uint32_t aAddr[3], bAddr[3];
    #pragma unroll
    for (int s = 0; s < 3; s++) {
        aAddr[s] = sbase + s*STAGE + aOff;
        bAddr[s] = sbase + s*STAGE + bOff;
    }

    float d[4][4][4];
    #pragma unroll
    for (int i = 0; i < 4; i++)
        #pragma unroll
        for (int jx = 0; jx < 4; jx++)
            #pragma unroll
            for (int qx = 0; qx < 4; qx++) d[i][jx][qx] = 0.f;

    auto issue_tile = [&](int i, int s) {
        uint32_t stA = sbase + s * STAGE;
        uint32_t stB = stA + 10240;
        #pragma unroll
        for (int q = 0; q < 2; q++) {
            int u = q * 256 + tid;           // 0..511
            int row = u >> 2, c16 = u & 3;
            cp16(stA + row * PITCH + c16 * 16,
                 g_Ah + (size_t)(m0 + row) * KEXT + i * 32 + c16 * 8);
            cp16(stB + row * PITCH + c16 * 16,
                 g_Bth + (size_t)(n0 + row) * KEXT + i * 32 + c16 * 8);
        }
        asm volatile("cp.async.commit_group;" ::: "memory");
    };

    issue_tile(0, 0);
    issue_tile(1, 1);

    int st = 0;
    for (int i = 0; i < 33; i++) {
        if (i < 32) asm volatile("cp.async.wait_group 1;" ::: "memory");
        else        asm volatile("cp.async.wait_group 0;" ::: "memory");
        __syncthreads();
        if (i + 2 <= 32) {
            int s2 = st + 2; if (s2 >= 3) s2 -= 3;
            issue_tile(i + 2, s2);
        }

        const uint32_t aS = aAddr[st], bS = bAddr[st];
        #pragma unroll
        for (int ks = 0; ks < 2; ks++) {
            uint32_t br[4][2];
            ldmx4(br[0][0], br[0][1], br[1][0], br[1][1], bS + ks*32);
            ldmx4(br[2][0], br[2][1], br[3][0], br[3][1], bS + 16*PITCH + ks*32);
            #pragma unroll
            for (int mf = 0; mf < 4; mf++) {
                uint32_t a0, a1, a2, a3;
                ldmx4(a0, a1, a2, a3, aS + mf*16*PITCH + ks*32);
                #pragma unroll
                for (int nf = 0; nf < 4; nf++)
                    mma_f16(d[mf][nf][0], d[mf][nf][1], d[mf][nf][2], d[mf][nf][3],
                            a0, a1, a2, a3, br[nf][0], br[nf][1]);
            }
        }
        if (++st == 3) st = 0;
    }

    // ---- epilogue: tanh + g-dot, reduce to e-partial ----
    float pr[4][2];
    #pragma unroll
    for (int mf = 0; mf < 4; mf++) { pr[mf][0] = 0.f; pr[mf][1] = 0.f; }

    #pragma unroll
    for (int mf = 0; mf < 4; mf++) {
        int r_lo = wm * 64 + mf * 16 + g;
        int bi_lo = ((m0 + r_lo) / NT == bA) ? 0 : 1;
        int bi_hi = ((m0 + r_lo + 8) / NT == bA) ? 0 : 1;
        #pragma unroll
        for (int nf = 0; nf < 4; nf++) {
            #pragma unroll
            for (int jx = 0; jx < 4; jx++) {
                int colL = wn * 32 + nf * 8 + 2 * c4 + (jx & 1);
                int bi = (jx >= 2) ? bi_hi : bi_lo;
                float v = d[mf][nf][jx] + biasS[bi][colL];
                pr[mf][jx >= 2] = fmaf(fast_tanh(v), gS[colL], pr[mf][jx >= 2]);
            }
        }
    }
    #pragma unroll
    for (int mf = 0; mf < 4; mf++) {
        #pragma unroll
        for (int h = 0; h < 2; h++) {
            pr[mf][h] += __shfl_xor_sync(0xffffffffu, pr[mf][h], 1);
            pr[mf][h] += __shfl_xor_sync(0xffffffffu, pr[mf][h], 2);
        }
    }
    if (c4 == 0) {
        #pragma unroll
        for (int mf = 0; mf < 4; mf++) {
            e_buf[wn][wm * 64 + mf * 16 + g]     = pr[mf][0];
            e_buf[wn][wm * 64 + mf * 16 + g + 8] = pr[mf][1];
        }
    }
    __syncthreads();
    if (tid < 128)
        g_e4[blockIdx.x * MROWS + m0 + tid] =
            (e_buf[0][tid] + e_buf[1][tid]) + (e_buf[2][tid] + e_buf[3][tid]);
}

// ---------------------------------------------------------------------------
// ctx_fused: per (b, chunk of 80 t): recompute row softmax stats from g_e4,
// emit attn for own chunk, then ctx partial accumulation.
// ---------------------------------------------------------------------------
__global__ void ctx_fused(const int* __restrict__ enc_len,
                          float* __restrict__ attn_dst, int write_attn) {
    __shared__ float red[256];
    __shared__ float aw[80];
    const int b = blockIdx.x, chunk = blockIdx.y;
    const int len = enc_len[b];
    const int t0 = chunk * 80;
    const int tid = threadIdx.x;

    if (t0 >= len) {            // fully masked: attn zeros only
        if (write_attn && tid < 80) attn_dst[b*NT + t0 + tid] = 0.f;
        return;
    }
    const float* e0 = g_e4 + b * NT;

    float m = -1e30f;
    for (int t = tid; t < NT; t += 256)
        if (t < len) {
            float e = (e0[t] + e0[MROWS + t]) + (e0[2*MROWS + t] + e0[3*MROWS + t]);
            m = fmaxf(m, 2.f * e);
        }
    red[tid] = m; __syncthreads();
    for (int s = 128; s > 0; s >>= 1) {
        if (tid < s) red[tid] = fmaxf(red[tid], red[tid+s]);
        __syncthreads();
    }
    m = red[0]; __syncthreads();

    float sum = 0.f;
    for (int t = tid; t < NT; t += 256)
        if (t < len) {
            float e = (e0[t] + e0[MROWS + t]) + (e0[2*MROWS + t] + e0[3*MROWS + t]);
            sum += expf(2.f * e - m);
        }
    red[tid] = sum; __syncthreads();
    for (int s = 128; s > 0; s >>= 1) {
        if (tid < s) red[tid] += red[tid+s];
        __syncthreads();
    }
    float inv = 1.f / red[0];

    if (tid < 80) {
        int t = t0 + tid;
        float v = 0.f;
        if (t < len) {
            float e = (e0[t] + e0[MROWS + t]) + (e0[2*MROWS + t] + e0[3*MROWS + t]);
            v = expf(2.f * e - m) * inv;
        }
        aw[tid] = v;
        if (write_attn) attn_dst[b*NT + t] = v;
    }
    __syncthreads();

    // ctx accumulate: 80 rows, 8 per iteration (MLP 8), fp16 enc reads
    int d0 = tid * 4;
    float a0 = 0.f, a1 = 0.f, a2 = 0.f, a3 = 0.f;
    const __half* base = g_Ah + (size_t)b * NT * KEXT + d0;
    #pragma unroll 1
    for (int i = 0; i < 10; i++) {
        int t = t0 + i * 8;
        uint2 v[8];
        #pragma unroll
        for (int r = 0; r < 8; r++)
            v[r] = *reinterpret_cast<const uint2*>(base + (size_t)(t + r) * KEXT);
        #pragma unroll
        for (int r = 0; r < 8; r++) {
            float w = aw[i * 8 + r];
            float2 p = __half22float2(*reinterpret_cast<__half2*>(&v[r].x));
            float2 q = __half22float2(*reinterpret_cast<__half2*>(&v[r].y));
            a0 = fmaf(w, p.x, a0); a1 = fmaf(w, p.y, a1);
            a2 = fmaf(w, q.x, a2); a3 = fmaf(w, q.y, a3);
        }
    }
    atomicAdd(&g_ctx[b*ED + d0 + 0], a0);
    atomicAdd(&g_ctx[b*ED + d0 + 1], a1);
    atomicAdd(&g_ctx[b*ED + d0 + 2], a2);
    atomicAdd(&g_ctx[b*ED + d0 + 3], a3);
}

// ---------------------------------------------------------------------------
// out: grid (8 bg, 32 og) = 256 blocks, block 256 = 32 o-cols x 8 d-slices.
// 4 batches per block; serial chain 16 iters; full-chip occupancy.
// ---------------------------------------------------------------------------
__global__ __launch_bounds__(256)
void out_kernel(const float* __restrict__ W_o,
                const float* __restrict__ b_o,
                float* __restrict__ c_dst, int write_c) {
    __shared__ float cs[4][ED];        // 16KB
    __shared__ float red[8][32][4];    // 4KB
    if (!write_c) return;
    const int tid = threadIdx.x;
    const int bg = blockIdx.x;         // 0..7 (4 b's each)
    const int ol = tid & 31;
    const int o = blockIdx.y * 32 + ol;
    const int sl = tid >> 5;           // 0..7 (128 d each)

    for (int i = tid; i < 1024; i += 256)
        reinterpret_cast<float4*>(&cs[0][0])[i] =
            reinterpret_cast<const float4*>(g_ctx + (size_t)bg * 4 * ED)[i];
    __syncthreads();

    float acc[4] = {0.f, 0.f, 0.f, 0.f};
    #pragma unroll 1
    for (int dd = 0; dd < 128; dd += 8) {
        int d = sl * 128 + dd;
        float w[8];
        #pragma unroll
        for (int u = 0; u < 8; u++) w[u] = W_o[(d + u) * OD + o];
        #pragma unroll
        for (int j = 0; j < 4; j++)
            #pragma unroll
            for (int u = 0; u < 8; u++)
                acc[j] = fmaf(cs[j][d + u], w[u], acc[j]);
    }
    #pragma unroll
    for (int j = 0; j < 4; j++) red[sl][ol][j] = acc[j];
    __syncthreads();
    if (sl == 0) {
        float base = b_o[o];
        #pragma unroll
        for (int j = 0; j < 4; j++)
            c_dst[(bg * 4 + j) * OD + o] = base +
                ((red[0][ol][j] + red[1][ol][j]) + (red[2][ol][j] + red[3][ol][j])) +
                ((red[4][ol][j] + red[5][ol][j]) + (red[6][ol][j] + red[7][ol][j]));
    }
}

// ---------------------------------------------------------------------------
extern "C" void kernel_launch(void* const* d_in, const int* in_sizes, int n_in,
                              void* d_out, int out_size) {
    const float* enc_pad  = (const float*)d_in[0];
    const int*   enc_len  = (const int*)  d_in[1];
    const float* dec_h    = (const float*)d_in[2];
    const float* att_prev = (const float*)d_in[3];
    const float* W_enc    = (const float*)d_in[4];
    const float* b_enc    = (const float*)d_in[5];
    const float* W_dec    = (const float*)d_in[6];
    const float* b_dec    = (const float*)d_in[7];
    const float* W_att    = (const float*)d_in[8];
    const float* b_att    = (const float*)d_in[9];
    const float* conv_w   = (const float*)d_in[10];
    const float* gvec     = (const float*)d_in[11];
    const float* W_o      = (const float*)d_in[12];
    const float* b_o      = (const float*)d_in[13];

    float* out = (float*)d_out;
    float* c_dst    = out;
    float* attn_dst = out;
    int write_c = 0, write_attn = 0;
    if (out_size >= NB*OD + NB*NT) {
        c_dst = out; attn_dst = out + NB*OD;
        write_c = 1; write_attn = 1;
    } else if (out_size == NB*NT) {
        attn_dst = out; write_attn = 1;
    } else {
        c_dst = out; write_c = 1;
    }

    static int smem_set = 0;
    if (!smem_set) {
        cudaFuncSetAttribute(gemm_e_mma, cudaFuncAttributeMaxDynamicSharedMemorySize, DYN_SMEM);
        smem_set = 1;
    }

    prep_all2<<<2800, 256, 16384>>>(enc_pad, att_prev, conv_w, enc_len,
                                    W_enc, W_att, dec_h, W_dec, b_dec, b_enc, b_att);
    gemm_e_mma<<<dim3(4, 500), 256, DYN_SMEM>>>(gvec, enc_len);
    ctx_fused<<<dim3(NB, 25), 256>>>(enc_len, attn_dst, write_attn);
    out_kernel<<<dim3(8, 32), 256>>>(W_o, b_o, c_dst, write_c);
}

// round 17
// speedup vs baseline: 2.3080x; 1.0184x over previous
#include <cuda_runtime.h>
#include <cuda_fp16.h>
#include <cstdint>
#include <math.h>

#define NB 32
#define NT 2000
#define ED 1024
#define AD 512
#define CCH 32
#define KHALF 50
#define KW 101
#define OD 1024
#define MROWS (NB*NT)     /* 64000 */
#define KEXT (ED + CCH)   /* 1056 */

// ---------------- device scratch (zero-initialized device globals) ----------
__device__ __align__(128) __half g_Ah[(size_t)MROWS * KEXT];  // enc || conv, fp16
__device__ __align__(128) __half g_Bth[AD * KEXT];            // [n][k] fp16
__device__ float g_bias[NB * AD];
__device__ float g_e4[4 * MROWS];                             // per-Nblock partial e
__device__ float g_ctx[NB * ED];

// ---------------- helpers ----------------
__device__ __forceinline__ void cp16(uint32_t dst, const void* src) {
    asm volatile("cp.async.cg.shared.global [%0], [%1], 16;" :: "r"(dst), "l"(src) : "memory");
}
__device__ __forceinline__ uint32_t smem_u32(const void* p) {
    uint32_t a;
    asm("{ .reg .u64 t; cvta.to.shared.u64 t, %1; cvt.u32.u64 %0, t; }" : "=r"(a) : "l"(p));
    return a;
}
__device__ __forceinline__ uint32_t h2u(__half2 h) {
    return *reinterpret_cast<uint32_t*>(&h);
}
__device__ __forceinline__ float fast_tanh(float x) {
    float y; asm("tanh.approx.f32 %0, %1;" : "=f"(y) : "f"(x)); return y;
}
__device__ __forceinline__ void ldmx4(uint32_t& r0, uint32_t& r1, uint32_t& r2, uint32_t& r3,
                                      uint32_t addr) {
    asm volatile("ldmatrix.sync.aligned.m8n8.x4.shared.b16 {%0,%1,%2,%3}, [%4];"
                 : "=r"(r0), "=r"(r1), "=r"(r2), "=r"(r3) : "r"(addr));
}
__device__ __forceinline__ void mma_f16(float& d0, float& d1, float& d2, float& d3,
                                        uint32_t a0, uint32_t a1, uint32_t a2, uint32_t a3,
                                        uint32_t b0, uint32_t b1) {
    asm volatile(
        "mma.sync.aligned.m16n8k16.row.col.f32.f16.f16.f32 "
        "{%0,%1,%2,%3},{%4,%5,%6,%7},{%8,%9},{%0,%1,%2,%3};"
        : "+f"(d0), "+f"(d1), "+f"(d2), "+f"(d3)
        : "r"(a0), "r"(a1), "r"(a2), "r"(a3), "r"(b0), "r"(b1));
}

// ---------------------------------------------------------------------------
// prep_all2: ONE lean grid (2800 blocks x 256 thr, 16KB DYNAMIC smem):
//   [0,2000)    enc -> fp16 g_Ah cols 0..1023 (no smem, streaming; mask-skip)
//   [2000,2256) location conv -> g_Ah cols 1024..1055 (14.3KB smem; mask-skip)
//   [2256,2784) B' transpose -> g_Bth fp16 (4.2KB smem)
//   [2784,2800) bias (4 batches/block, 16KB smem) + zero g_ctx
// ---------------------------------------------------------------------------
__global__ __launch_bounds__(256)
void prep_all2(const float* __restrict__ enc,
               const float* __restrict__ att_prev,
               const float* __restrict__ conv_w,
               const int* __restrict__ enc_len,
               const float* __restrict__ W_enc,
               const float* __restrict__ W_att,
               const float* __restrict__ dec_h,
               const float* __restrict__ W_dec,
               const float* __restrict__ b_dec,
               const float* __restrict__ b_enc,
               const float* __restrict__ b_att) {
    extern __shared__ float dynf[];
    const int tid = threadIdx.x;
    const int bid = blockIdx.x;

    if (bid < 2000) {
        const int r0 = bid * 32;
        const int b0 = r0 / NT, b1 = (r0 + 31) / NT;
        if (b0 == b1 && (r0 - b0 * NT) >= __ldg(&enc_len[b0])) return;
        #pragma unroll 4
        for (int q = 0; q < 32; q++) {
            int row = q, c4 = tid;
            float4 v = *reinterpret_cast<const float4*>(enc + (size_t)(r0 + row) * ED + c4 * 4);
            uint2 pk = make_uint2(h2u(__floats2half2_rn(v.x, v.y)),
                                  h2u(__floats2half2_rn(v.z, v.w)));
            *reinterpret_cast<uint2*>(g_Ah + (size_t)(r0 + row) * KEXT + c4 * 4) = pk;
        }
    } else if (bid < 2256) {
        float* ap = dynf;
        float* wk = dynf + 352;
        int idx = bid - 2000;
        int b = idx >> 3;
        int t0 = (idx & 7) * 250;
        if (t0 >= __ldg(&enc_len[b])) return;
        for (int i = tid; i < 350; i += 256) {
            int gpos = t0 - KHALF + i;
            ap[i] = (gpos >= 0 && gpos < NT) ? att_prev[b * NT + gpos] : 0.f;
        }
        for (int i = tid; i < CCH * KW; i += 256) wk[i] = conv_w[i];
        __syncthreads();
        if (tid < 250) {
            float s[CCH];
            #pragma unroll
            for (int c = 0; c < CCH; c++) s[c] = 0.f;
            for (int k = 0; k < KW; k++) {
                float av = ap[tid + k];
                #pragma unroll
                for (int c = 0; c < CCH; c++) s[c] = fmaf(av, wk[c * KW + k], s[c]);
            }
            uint32_t u32[16];
            #pragma unroll
            for (int k = 0; k < 16; k++) u32[k] = h2u(__floats2half2_rn(s[2*k], s[2*k+1]));
            uint4* dst = reinterpret_cast<uint4*>(g_Ah + (size_t)(b * NT + t0 + tid) * KEXT + ED);
            dst[0] = make_uint4(u32[0], u32[1], u32[2], u32[3]);
            dst[1] = make_uint4(u32[4], u32[5], u32[6], u32[7]);
            dst[2] = make_uint4(u32[8], u32[9], u32[10], u32[11]);
            dst[3] = make_uint4(u32[12], u32[13], u32[14], u32[15]);
        }
    } else if (bid < 2784) {
        float* sm = dynf;
        int idx = bid - 2256;
        int kb = idx % 33, nb = idx / 33;
        int tx = tid & 31, ty8 = tid >> 5;
        #pragma unroll
        for (int r = ty8; r < 32; r += 8) {
            int k = kb * 32 + r;
            int n = nb * 32 + tx;
            sm[r * 33 + tx] = (k < ED) ? W_enc[k * AD + n] : W_att[(k - ED) * AD + n];
        }
        __syncthreads();
        #pragma unroll
        for (int r = ty8; r < 32; r += 8)
            g_Bth[(size_t)(nb * 32 + r) * KEXT + kb * 32 + tx] =
                __float2half_rn(sm[tx * 33 + r]);
    } else {
        float* ds = dynf;                 // 16KB
        int idx = bid - 2784;             // 0..15
        int bg = idx >> 1;                // 0..7 (4 b's each)
        int half = idx & 1;
        int a = half * 256 + tid;
        for (int i = tid; i < 1024; i += 256)
            reinterpret_cast<float4*>(ds)[i] =
                reinterpret_cast<const float4*>(dec_h + (size_t)bg * 4 * ED)[i];
        for (int i = tid; i < 2048; i += 256) g_ctx[idx * 2048 + i] = 0.f;
        __syncthreads();
        float acc0 = 0.f, acc1 = 0.f, acc2 = 0.f, acc3 = 0.f;
        #pragma unroll 8
        for (int d = 0; d < ED; d++) {
            float w = W_dec[d * AD + a];
            acc0 = fmaf(ds[d], w, acc0);
            acc1 = fmaf(ds[ED + d], w, acc1);
            acc2 = fmaf(ds[2*ED + d], w, acc2);
            acc3 = fmaf(ds[3*ED + d], w, acc3);
        }
        float base = b_dec[a] + b_enc[a] + b_att[a];
        g_bias[(bg * 4 + 0) * AD + a] = base + acc0;
        g_bias[(bg * 4 + 1) * AD + a] = base + acc1;
        g_bias[(bg * 4 + 2) * AD + a] = base + acc2;
        g_bias[(bg * 4 + 3) * AD + a] = base + acc3;
    }
}

// ---------------------------------------------------------------------------
// Main GEMM (mma.sync fp16 m16n8k16 + ldmatrix), masked-CTA early exit.
// [at legacy-HMMA effective ceiling (~12.7cyc/MMA): ~181us, frozen]
// ---------------------------------------------------------------------------
#define PITCH 80
#define STAGE 20480            /* A 10240 + B 10240 */
#define DYN_SMEM (3*STAGE)

__global__ __launch_bounds__(256, 2)
void gemm_e_mma(const float* __restrict__ gv, const int* __restrict__ enc_len) {
    extern __shared__ char dyn[];
    __shared__ float gS[128];
    __shared__ float biasS[2][128];
    __shared__ float e_buf[4][128];

    const int tid = threadIdx.x, lane = tid & 31, wid = tid >> 5;
    const int wm = wid >> 2, wn = wid & 3;
    const int g = lane >> 2, c4 = lane & 3;
    const int n0 = blockIdx.x * 128;
    const int m0 = blockIdx.y * 128;
    const int bA = m0 / NT, bB = (m0 + 127) / NT;
    if (bA == bB && (m0 - bA * NT) >= __ldg(&enc_len[bA])) return;

    const uint32_t sbase = smem_u32(dyn);

    if (tid < 128) {
        gS[tid] = gv[n0 + tid];
        biasS[0][tid] = g_bias[bA*AD + n0 + tid];
    } else {
        biasS[1][tid-128] = g_bias[bB*AD + n0 + tid - 128];
    }

    const uint32_t aOff = (uint32_t)((wm*64 + (lane & 15)) * PITCH + ((lane >> 4) & 1) * 16);
    const uint32_t bOff = 10240u +
        (uint32_t)((wn*32 + (lane & 7) + ((lane >> 4) & 1) * 8) * PITCH + ((lane >> 3) & 1) * 16);
    uint32_t aAddr[3], bAddr[3];
    #pragma unroll
    for (int s = 0; s < 3; s++) {
        aAddr[s] = sbase + s*STAGE + aOff;
        bAddr[s] = sbase + s*STAGE + bOff;
    }

    float d[4][4][4];
    #pragma unroll
    for (int i = 0; i < 4; i++)
        #pragma unroll
        for (int jx = 0; jx < 4; jx++)
            #pragma unroll
            for (int qx = 0; qx < 4; qx++) d[i][jx][qx] = 0.f;

    auto issue_tile = [&](int i, int s) {
        uint32_t stA = sbase + s * STAGE;
        uint32_t stB = stA + 10240;
        #pragma unroll
        for (int q = 0; q < 2; q++) {
            int u = q * 256 + tid;           // 0..511
            int row = u >> 2, c16 = u & 3;
            cp16(stA + row * PITCH + c16 * 16,
                 g_Ah + (size_t)(m0 + row) * KEXT + i * 32 + c16 * 8);
            cp16(stB + row * PITCH + c16 * 16,
                 g_Bth + (size_t)(n0 + row) * KEXT + i * 32 + c16 * 8);
        }
        asm volatile("cp.async.commit_group;" ::: "memory");
    };

    issue_tile(0, 0);
    issue_tile(1, 1);

    int st = 0;
    for (int i = 0; i < 33; i++) {
        if (i < 32) asm volatile("cp.async.wait_group 1;" ::: "memory");
        else        asm volatile("cp.async.wait_group 0;" ::: "memory");
        __syncthreads();
        if (i + 2 <= 32) {
            int s2 = st + 2; if (s2 >= 3) s2 -= 3;
            issue_tile(i + 2, s2);
        }

        const uint32_t aS = aAddr[st], bS = bAddr[st];
        #pragma unroll
        for (int ks = 0; ks < 2; ks++) {
            uint32_t br[4][2];
            ldmx4(br[0][0], br[0][1], br[1][0], br[1][1], bS + ks*32);
            ldmx4(br[2][0], br[2][1], br[3][0], br[3][1], bS + 16*PITCH + ks*32);
            #pragma unroll
            for (int mf = 0; mf < 4; mf++) {
                uint32_t a0, a1, a2, a3;
                ldmx4(a0, a1, a2, a3, aS + mf*16*PITCH + ks*32);
                #pragma unroll
                for (int nf = 0; nf < 4; nf++)
                    mma_f16(d[mf][nf][0], d[mf][nf][1], d[mf][nf][2], d[mf][nf][3],
                            a0, a1, a2, a3, br[nf][0], br[nf][1]);
            }
        }
        if (++st == 3) st = 0;
    }

    // ---- epilogue: tanh + g-dot, reduce to e-partial ----
    float pr[4][2];
    #pragma unroll
    for (int mf = 0; mf < 4; mf++) { pr[mf][0] = 0.f; pr[mf][1] = 0.f; }

    #pragma unroll
    for (int mf = 0; mf < 4; mf++) {
        int r_lo = wm * 64 + mf * 16 + g;
        int bi_lo = ((m0 + r_lo) / NT == bA) ? 0 : 1;
        int bi_hi = ((m0 + r_lo + 8) / NT == bA) ? 0 : 1;
        #pragma unroll
        for (int nf = 0; nf < 4; nf++) {
            #pragma unroll
            for (int jx = 0; jx < 4; jx++) {
                int colL = wn * 32 + nf * 8 + 2 * c4 + (jx & 1);
                int bi = (jx >= 2) ? bi_hi : bi_lo;
                float v = d[mf][nf][jx] + biasS[bi][colL];
                pr[mf][jx >= 2] = fmaf(fast_tanh(v), gS[colL], pr[mf][jx >= 2]);
            }
        }
    }
    #pragma unroll
    for (int mf = 0; mf < 4; mf++) {
        #pragma unroll
        for (int h = 0; h < 2; h++) {
            pr[mf][h] += __shfl_xor_sync(0xffffffffu, pr[mf][h], 1);
            pr[mf][h] += __shfl_xor_sync(0xffffffffu, pr[mf][h], 2);
        }
    }
    if (c4 == 0) {
        #pragma unroll
        for (int mf = 0; mf < 4; mf++) {
            e_buf[wn][wm * 64 + mf * 16 + g]     = pr[mf][0];
            e_buf[wn][wm * 64 + mf * 16 + g + 8] = pr[mf][1];
        }
    }
    __syncthreads();
    if (tid < 128)
        g_e4[blockIdx.x * MROWS + m0 + tid] =
            (e_buf[0][tid] + e_buf[1][tid]) + (e_buf[2][tid] + e_buf[3][tid]);
}

// ---------------------------------------------------------------------------
// ctx_fused: per (b, chunk of 80 t): recompute row softmax stats from g_e4,
// emit attn for own chunk, then ctx partial accumulation.
// ---------------------------------------------------------------------------
__global__ void ctx_fused(const int* __restrict__ enc_len,
                          float* __restrict__ attn_dst, int write_attn) {
    __shared__ float red[256];
    __shared__ float aw[80];
    const int b = blockIdx.x, chunk = blockIdx.y;
    const int len = enc_len[b];
    const int t0 = chunk * 80;
    const int tid = threadIdx.x;

    if (t0 >= len) {            // fully masked: attn zeros only
        if (write_attn && tid < 80) attn_dst[b*NT + t0 + tid] = 0.f;
        return;
    }
    const float* e0 = g_e4 + b * NT;

    float m = -1e30f;
    for (int t = tid; t < len; t += 256) {
        float e = (e0[t] + e0[MROWS + t]) + (e0[2*MROWS + t] + e0[3*MROWS + t]);
        m = fmaxf(m, 2.f * e);
    }
    red[tid] = m; __syncthreads();
    for (int s = 128; s > 0; s >>= 1) {
        if (tid < s) red[tid] = fmaxf(red[tid], red[tid+s]);
        __syncthreads();
    }
    m = red[0]; __syncthreads();

    float sum = 0.f;
    for (int t = tid; t < len; t += 256) {
        float e = (e0[t] + e0[MROWS + t]) + (e0[2*MROWS + t] + e0[3*MROWS + t]);
        sum += expf(2.f * e - m);
    }
    red[tid] = sum; __syncthreads();
    for (int s = 128; s > 0; s >>= 1) {
        if (tid < s) red[tid] += red[tid+s];
        __syncthreads();
    }
    float inv = 1.f / red[0];

    if (tid < 80) {
        int t = t0 + tid;
        float v = 0.f;
        if (t < len) {
            float e = (e0[t] + e0[MROWS + t]) + (e0[2*MROWS + t] + e0[3*MROWS + t]);
            v = expf(2.f * e - m) * inv;
        }
        aw[tid] = v;
        if (write_attn) attn_dst[b*NT + t] = v;
    }
    __syncthreads();

    // ctx accumulate: 80 rows, 8 per iteration (MLP 8), fp16 enc reads
    int d0 = tid * 4;
    float a0 = 0.f, a1 = 0.f, a2 = 0.f, a3 = 0.f;
    const __half* base = g_Ah + (size_t)b * NT * KEXT + d0;
    #pragma unroll 1
    for (int i = 0; i < 10; i++) {
        int t = t0 + i * 8;
        uint2 v[8];
        #pragma unroll
        for (int r = 0; r < 8; r++)
            v[r] = *reinterpret_cast<const uint2*>(base + (size_t)(t + r) * KEXT);
        #pragma unroll
        for (int r = 0; r < 8; r++) {
            float w = aw[i * 8 + r];
            float2 p = __half22float2(*reinterpret_cast<__half2*>(&v[r].x));
            float2 q = __half22float2(*reinterpret_cast<__half2*>(&v[r].y));
            a0 = fmaf(w, p.x, a0); a1 = fmaf(w, p.y, a1);
            a2 = fmaf(w, q.x, a2); a3 = fmaf(w, q.y, a3);
        }
    }
    atomicAdd(&g_ctx[b*ED + d0 + 0], a0);
    atomicAdd(&g_ctx[b*ED + d0 + 1], a1);
    atomicAdd(&g_ctx[b*ED + d0 + 2], a2);
    atomicAdd(&g_ctx[b*ED + d0 + 3], a3);
}

// ---------------------------------------------------------------------------
// out: grid (8 bg, 32 og) = 256 blocks, block 512 = 32 o-cols x 16 d-slices.
// Serial LDG chain per thread: 8 iterations of 8 batched loads.
// ---------------------------------------------------------------------------
__global__ __launch_bounds__(512)
void out_kernel(const float* __restrict__ W_o,
                const float* __restrict__ b_o,
                float* __restrict__ c_dst, int write_c) {
    __shared__ float cs[4][ED];        // 16KB
    __shared__ float red[16][32][4];   // 8KB
    if (!write_c) return;
    const int tid = threadIdx.x;
    const int bg = blockIdx.x;         // 0..7 (4 b's each)
    const int ol = tid & 31;
    const int o = blockIdx.y * 32 + ol;
    const int sl = tid >> 5;           // 0..15 (64 d each)

    for (int i = tid; i < 1024; i += 512)
        reinterpret_cast<float4*>(&cs[0][0])[i] =
            reinterpret_cast<const float4*>(g_ctx + (size_t)bg * 4 * ED)[i];
    __syncthreads();

    float acc[4] = {0.f, 0.f, 0.f, 0.f};
    #pragma unroll 1
    for (int dd = 0; dd < 64; dd += 8) {
        int d = sl * 64 + dd;
        float w[8];
        #pragma unroll
        for (int u = 0; u < 8; u++) w[u] = W_o[(d + u) * OD + o];
        #pragma unroll
        for (int j = 0; j < 4; j++)
            #pragma unroll
            for (int u = 0; u < 8; u++)
                acc[j] = fmaf(cs[j][d + u], w[u], acc[j]);
    }
    #pragma unroll
    for (int j = 0; j < 4; j++) red[sl][ol][j] = acc[j];
    __syncthreads();
    if (sl == 0) {
        float base = b_o[o];
        #pragma unroll
        for (int j = 0; j < 4; j++) {
            float s01 = (red[0][ol][j] + red[1][ol][j]) + (red[2][ol][j] + red[3][ol][j]);
            float s23 = (red[4][ol][j] + red[5][ol][j]) + (red[6][ol][j] + red[7][ol][j]);
            float s45 = (red[8][ol][j] + red[9][ol][j]) + (red[10][ol][j] + red[11][ol][j]);
            float s67 = (red[12][ol][j] + red[13][ol][j]) + (red[14][ol][j] + red[15][ol][j]);
            c_dst[(bg * 4 + j) * OD + o] = base + (s01 + s23) + (s45 + s67);
        }
    }
}

// ---------------------------------------------------------------------------
extern "C" void kernel_launch(void* const* d_in, const int* in_sizes, int n_in,
                              void* d_out, int out_size) {
    const float* enc_pad  = (const float*)d_in[0];
    const int*   enc_len  = (const int*)  d_in[1];
    const float* dec_h    = (const float*)d_in[2];
    const float* att_prev = (const float*)d_in[3];
    const float* W_enc    = (const float*)d_in[4];
    const float* b_enc    = (const float*)d_in[5];
    const float* W_dec    = (const float*)d_in[6];
    const float* b_dec    = (const float*)d_in[7];
    const float* W_att    = (const float*)d_in[8];
    const float* b_att    = (const float*)d_in[9];
    const float* conv_w   = (const float*)d_in[10];
    const float* gvec     = (const float*)d_in[11];
    const float* W_o      = (const float*)d_in[12];
    const float* b_o      = (const float*)d_in[13];

    float* out = (float*)d_out;
    float* c_dst    = out;
    float* attn_dst = out;
    int write_c = 0, write_attn = 0;
    if (out_size >= NB*OD + NB*NT) {
        c_dst = out; attn_dst = out + NB*OD;
        write_c = 1; write_attn = 1;
    } else if (out_size == NB*NT) {
        attn_dst = out; write_attn = 1;
    } else {
        c_dst = out; write_c = 1;
    }

    static int smem_set = 0;
    if (!smem_set) {
        cudaFuncSetAttribute(gemm_e_mma, cudaFuncAttributeMaxDynamicSharedMemorySize, DYN_SMEM);
        smem_set = 1;
    }

    prep_all2<<<2800, 256, 16384>>>(enc_pad, att_prev, conv_w, enc_len,
                                    W_enc, W_att, dec_h, W_dec, b_dec, b_enc, b_att);
    gemm_e_mma<<<dim3(4, 500), 256, DYN_SMEM>>>(gvec, enc_len);
    ctx_fused<<<dim3(NB, 25), 256>>>(enc_len, attn_dst, write_attn);
    out_kernel<<<dim3(8, 32), 512>>>(W_o, b_o, c_dst, write_c);
}